// round 12
// baseline (speedup 1.0000x reference)
#include <cuda_runtime.h>
#include <cuda_bf16.h>
#include <math.h>
#include <stdint.h>

#define Bn  2
#define Tn  2048
#define Dn  1024
#define Hn  16
#define HDn 64
#define M_TOT 4096
#define N_QKV 3072

// -------- scratch (device globals: allocation-free) --------
__device__ __nv_bfloat16 g_q[(size_t)Bn*Hn*Tn*HDn];           // [b,h][t][d]
__device__ __nv_bfloat16 g_k[(size_t)Bn*Hn*Tn*HDn];           // [b,h][t][d]
__device__ __nv_bfloat16 g_vt[(size_t)Bn*Hn*HDn*Tn];          // [b,h][d][t]
__device__ __nv_bfloat16 g_yb[(size_t)M_TOT*Dn];              // attention out bf16
__device__ __nv_bfloat16 g_xb[(size_t)M_TOT*Dn];              // x bf16
__device__ __nv_bfloat16 g_wpt[(size_t)N_QKV*Dn];             // W_proj^T bf16 [N][K]
__device__ __nv_bfloat16 g_wot[(size_t)Dn*Dn];                // W_out^T  bf16 [N][K]
__device__ float g_z[(size_t)M_TOT*Dn];
__device__ int   g_cnt[M_TOT/128];                             // proj m-tile counters

// ---------------- helpers ----------------
__device__ __forceinline__ uint32_t pack_bf16(float lo, float hi) {
    uint32_t r;
    asm("cvt.rn.bf16x2.f32 %0, %1, %2;" : "=r"(r) : "f"(hi), "f"(lo));
    return r;
}

__device__ __forceinline__ void mma_bf16(float d[4],
                                         uint32_t a0, uint32_t a1, uint32_t a2, uint32_t a3,
                                         uint32_t b0, uint32_t b1) {
    asm volatile(
        "mma.sync.aligned.m16n8k16.row.col.f32.bf16.bf16.f32 "
        "{%0,%1,%2,%3}, {%4,%5,%6,%7}, {%8,%9}, {%0,%1,%2,%3};\n"
        : "+f"(d[0]), "+f"(d[1]), "+f"(d[2]), "+f"(d[3])
        : "r"(a0), "r"(a1), "r"(a2), "r"(a3), "r"(b0), "r"(b1));
}

__device__ __forceinline__ void ldsm4(uint32_t& r0, uint32_t& r1,
                                      uint32_t& r2, uint32_t& r3, uint32_t addr) {
    asm volatile("ldmatrix.sync.aligned.m8n8.x4.shared.b16 {%0,%1,%2,%3}, [%4];"
                 : "=r"(r0), "=r"(r1), "=r"(r2), "=r"(r3) : "r"(addr));
}

__device__ __forceinline__ uint32_t smem_u32(const void* p) {
    uint32_t a;
    asm("{ .reg .u64 t; cvta.to.shared.u64 t, %1; cvt.u32.u64 %0, t; }"
        : "=r"(a) : "l"(p));
    return a;
}

__device__ __forceinline__ void cp16(uint32_t dst, const void* src) {
    asm volatile("cp.async.cg.shared.global [%0], [%1], 16;"
                 :: "r"(dst), "l"(src) : "memory");
}
#define CP_COMMIT() asm volatile("cp.async.commit_group;" ::: "memory")
#define CP_WAIT2()  asm volatile("cp.async.wait_group 2;" ::: "memory")
#define CP_WAIT0()  asm volatile("cp.async.wait_group 0;" ::: "memory")

__device__ __forceinline__ float4 ldcg4(const float* p) {
    float4 v;
    asm volatile("ld.global.cg.v4.f32 {%0,%1,%2,%3}, [%4];"
                 : "=f"(v.x), "=f"(v.y), "=f"(v.z), "=f"(v.w) : "l"(p));
    return v;
}

// ============================================================
// prep_all: x->bf16, Wp^T, Wo^T, zero counters — ONE kernel
// ============================================================
__device__ __forceinline__ void transpose_block(
    const float* __restrict__ W, uint32_t* __restrict__ Wt,
    int N, int n0, int k0, int tid, float (*tile)[33])
{
    const int tx = tid & 31, ty = tid >> 5;
    #pragma unroll
    for (int p = 0; p < 4; p++) {
        int r = ty + p * 8;
        tile[r][tx] = W[(size_t)(k0 + r) * N + n0 + tx];
    }
    __syncthreads();
    const int wx = tid & 15, wy = tid >> 4;
    #pragma unroll
    for (int p = 0; p < 2; p++) {
        int rowo = wy + p * 16;
        uint32_t wv = pack_bf16(tile[2*wx][rowo], tile[2*wx+1][rowo]);
        Wt[(((size_t)(n0 + rowo) * Dn + k0) >> 1) + wx] = wv;
    }
}

__global__ __launch_bounds__(256) void prep_all(
    const float* __restrict__ x, const float* __restrict__ Wp,
    const float* __restrict__ Wo)
{
    __shared__ float tile[32][33];
    const int id = blockIdx.x;
    const int tid = threadIdx.x;
    if (id < 2048) {
        size_t i = ((size_t)id * 256 + tid) * 8;
        float4 a = *(const float4*)(x + i);
        float4 b = *(const float4*)(x + i + 4);
        uint4 o;
        o.x = pack_bf16(a.x, a.y); o.y = pack_bf16(a.z, a.w);
        o.z = pack_bf16(b.x, b.y); o.w = pack_bf16(b.z, b.w);
        *(uint4*)((uint32_t*)g_xb + (i >> 1)) = o;
    } else if (id < 2048 + 96*32) {
        const int idx = id - 2048;
        transpose_block(Wp, (uint32_t*)g_wpt, N_QKV,
                        (idx % 96) * 32, (idx / 96) * 32, tid, tile);
    } else if (id < 2048 + 96*32 + 32*32) {
        const int idx = id - (2048 + 96*32);
        transpose_block(Wo, (uint32_t*)g_wot, Dn,
                        (idx % 32) * 32, (idx / 32) * 32, tid, tile);
    } else {
        if (tid < M_TOT/128) g_cnt[tid] = 0;
    }
}

// ============================================================
// bf16 HMMA GEMM: CTA 128x128, 256 thr, 2 CTAs/SM, 4-stage cp.async,
// one barrier per k16, B-fragment LDSMs hoisted ahead of MMAs.
// Proj variant fuses LayerNorm via per-m-tile completion counter.
// ============================================================
#define RSW 12                       // row stride words (48 B)
#define AST_W (128*RSW)              // 1536
#define STG_W (2*AST_W)              // 3072 words = 12 KB

template <int ND, bool IS_QKV>
__global__ __launch_bounds__(256, 2) void gemm_mma3(
    const float* __restrict__ bias, const float* __restrict__ Xres,
    const float* __restrict__ gam, const float* __restrict__ bet,
    float* __restrict__ out)
{
    extern __shared__ __align__(16) uint32_t sm3[];   // 4 * STG_W
    __shared__ int is_last;

    const int tid = threadIdx.x, lane = tid & 31, warp = tid >> 5;
    const int g = lane >> 2, tg = lane & 3;
    const int wm = (warp & 3) * 32;
    const int wn = (warp >> 2) * 64;
    const int m0 = blockIdx.y * 128, n0 = blockIdx.x * 128;

    const uint32_t* Aimg = (const uint32_t*)(IS_QKV ? g_xb : g_yb);
    const uint32_t* Bimg = (const uint32_t*)(IS_QKV ? g_wpt : g_wot);

    const uint32_t smb = smem_u32(sm3);

    const uint32_t a_ld = (wm + (lane & 15)) * 48 + ((lane >> 4) & 1) * 16;
    const uint32_t b_ld = AST_W*4 +
        (wn + (lane & 7) + ((lane >> 4) & 1) * 8) * 48 + ((lane >> 3) & 1) * 16;

    const int srow = tid >> 1, sch = tid & 1;

    float acc[2][8][4];
    #pragma unroll
    for (int i = 0; i < 2; i++)
        #pragma unroll
        for (int j = 0; j < 8; j++)
            #pragma unroll
            for (int e = 0; e < 4; e++) acc[i][j][e] = 0.f;

    auto stagef = [&](int kt) {
        uint32_t* st = sm3 + (kt & 3) * STG_W;
        cp16(smem_u32(st + srow*RSW + sch*4),
             Aimg + (size_t)(m0 + srow) * (Dn/2) + kt*8 + sch*4);
        cp16(smem_u32(st + AST_W + srow*RSW + sch*4),
             Bimg + (size_t)(n0 + srow) * (Dn/2) + kt*8 + sch*4);
        CP_COMMIT();
    };

    stagef(0); stagef(1); stagef(2);

    #pragma unroll 1
    for (int kt = 0; kt < 64; kt++) {
        if (kt <= 60) { CP_WAIT2(); } else { CP_WAIT0(); }
        __syncthreads();
        if (kt + 3 < 64) stagef(kt + 3);

        const uint32_t sb = smb + (kt & 3) * (STG_W * 4);

        uint32_t a[2][4], bfr[4][4];
        #pragma unroll
        for (int mt = 0; mt < 2; mt++)
            ldsm4(a[mt][0], a[mt][1], a[mt][2], a[mt][3], sb + a_ld + mt*768);
        #pragma unroll
        for (int nb = 0; nb < 4; nb++)
            ldsm4(bfr[nb][0], bfr[nb][1], bfr[nb][2], bfr[nb][3], sb + b_ld + nb*768);

        #pragma unroll
        for (int nb = 0; nb < 4; nb++) {
            #pragma unroll
            for (int mt = 0; mt < 2; mt++) {
                mma_bf16(acc[mt][nb*2+0], a[mt][0], a[mt][1], a[mt][2], a[mt][3],
                         bfr[nb][0], bfr[nb][1]);
                mma_bf16(acc[mt][nb*2+1], a[mt][0], a[mt][1], a[mt][2], a[mt][3],
                         bfr[nb][2], bfr[nb][3]);
            }
        }
    }

    const int ncb = n0 + wn;
    float2 bi[8];
    #pragma unroll
    for (int nt = 0; nt < 8; nt++)
        bi[nt] = *(const float2*)(bias + ncb + nt*8 + 2*tg);

    if (IS_QKV) {
        const int which = ncb >> 10;
        const int h = (ncb >> 6) & 15;
        if (which == 2) {
            const int dbase = ncb & 63;
            #pragma unroll
            for (int mt = 0; mt < 2; mt++) {
                #pragma unroll
                for (int hf = 0; hf < 2; hf++) {
                    const int m = m0 + wm + mt*16 + g + hf*8;
                    const int bb = m >> 11, t = m & 2047;
                    __nv_bfloat16* vt = g_vt + ((size_t)(bb*Hn + h) * 64) * Tn + t;
                    #pragma unroll
                    for (int nt = 0; nt < 8; nt++) {
                        const int d = dbase + nt*8 + 2*tg;
                        vt[(size_t)d*Tn]     = __float2bfloat16_rn(acc[mt][nt][hf*2+0] + bi[nt].x);
                        vt[(size_t)(d+1)*Tn] = __float2bfloat16_rn(acc[mt][nt][hf*2+1] + bi[nt].y);
                    }
                }
            }
        } else {
            const float scale = (which == 0) ? 0.125f : 1.f;
            uint32_t* base = (which == 0) ? (uint32_t*)g_q : (uint32_t*)g_k;
            #pragma unroll
            for (int mt = 0; mt < 2; mt++) {
                #pragma unroll
                for (int hf = 0; hf < 2; hf++) {
                    const int m = m0 + wm + mt*16 + g + hf*8;
                    const int b = m >> 11, t = m & 2047;
                    uint32_t* dst = base + ((size_t)(b*Hn + h)*Tn + t) * 32;
                    #pragma unroll
                    for (int nt = 0; nt < 8; nt++)
                        dst[nt*4 + tg] = pack_bf16(
                            (acc[mt][nt][hf*2+0] + bi[nt].x) * scale,
                            (acc[mt][nt][hf*2+1] + bi[nt].y) * scale);
                }
            }
        }
    } else {
        #pragma unroll
        for (int mt = 0; mt < 2; mt++) {
            #pragma unroll
            for (int hf = 0; hf < 2; hf++) {
                const int m = m0 + wm + mt*16 + g + hf*8;
                const float* xr = Xres + (size_t)m * Dn + ncb;
                float* zr = g_z + (size_t)m * Dn + ncb;
                #pragma unroll
                for (int nt = 0; nt < 8; nt++) {
                    const int off = nt*8 + 2*tg;
                    float2 xv = *(const float2*)(xr + off);
                    float2 o;
                    o.x = acc[mt][nt][hf*2+0] + bi[nt].x + xv.x;
                    o.y = acc[mt][nt][hf*2+1] + bi[nt].y + xv.y;
                    *(float2*)(zr + off) = o;
                }
            }
        }
        // ---- fused LayerNorm: last of the 8 n-tile CTAs per m-tile ----
        __threadfence();
        if (tid == 0) {
            int old = atomicAdd(&g_cnt[blockIdx.y], 1);
            is_last = (old == (Dn/128 - 1));
        }
        __syncthreads();
        if (is_last) {
            const int row  = m0 + (tid >> 1);
            const int col0 = (tid & 1) * 512;
            const float* zr = g_z + (size_t)row * Dn + col0;
            float s = 0.f, ss = 0.f;
            #pragma unroll 4
            for (int i = 0; i < 128; i++) {
                float4 v = ldcg4(zr + i*4);
                s  += v.x + v.y + v.z + v.w;
                ss += v.x*v.x + v.y*v.y + v.z*v.z + v.w*v.w;
            }
            s  += __shfl_xor_sync(0xffffffffu, s,  1);
            ss += __shfl_xor_sync(0xffffffffu, ss, 1);
            const float mu   = s * (1.f / Dn);
            const float var  = ss * (1.f / Dn) - mu * mu;
            const float rstd = rsqrtf(var + 1e-5f);
            float* outr = out + (size_t)row * Dn + col0;
            #pragma unroll 4
            for (int i = 0; i < 128; i++) {
                float4 v  = ldcg4(zr + i*4);
                float4 gv = *(const float4*)(gam + col0 + i*4);
                float4 bv = *(const float4*)(bet + col0 + i*4);
                float4 o;
                o.x = (v.x - mu)*rstd*gv.x + bv.x;
                o.y = (v.y - mu)*rstd*gv.y + bv.y;
                o.z = (v.z - mu)*rstd*gv.z + bv.z;
                o.w = (v.w - mu)*rstd*gv.w + bv.w;
                *(float4*)(outr + i*4) = o;
            }
        }
    }
}

// ============================================================
// Causal attention v3 (unchanged from R11)
// ============================================================
#define VW3 36                         // row stride in words (144 B)
#define P_OFF (128*VW3)
#define K_OFF (2*128*VW3)
#define V_OFF (K_OFF + 2*64*VW3)
#define ATT3_W (V_OFF + 2*64*VW3)      // 18432 words = 73728 B

__global__ __launch_bounds__(256, 2) void attn_v3()
{
    extern __shared__ __align__(16) uint32_t smA[];
    __shared__ float dsum[128];

    const int qb = (Tn/128 - 1) - blockIdx.x;
    const int h = blockIdx.y, b = blockIdx.z;
    const int tid = threadIdx.x, lane = tid & 31, warp = tid >> 5;
    const int g = lane >> 2, tg = lane & 3;
    const int band = warp >> 1, half = warp & 1;
    const int ib  = band * 32;
    const int jd0 = half * 32;

    const size_t headw = ((size_t)(b*Hn + h)) * Tn * 32;
    const uint32_t* qg  = (const uint32_t*)g_q + headw;
    const uint32_t* kg  = (const uint32_t*)g_k + headw;
    const uint32_t* vtg = (const uint32_t*)g_vt + (size_t)(b*Hn + h) * 64 * (Tn/2);

    const uint32_t smb = smem_u32(smA);

    const int lrow15 = lane & 15;
    const int lhi16  = ((lane >> 4) & 1) * 16;
    const int brow   = (lane & 7) + ((lane >> 4) & 1) * 8;
    const int bchk16 = ((lane >> 3) & 1) * 16;

    {
        const int r = tid >> 1, c0 = (tid & 1) * 16;
        const uint32_t dst = smb + (uint32_t)(r*VW3 + c0) * 4;
        const uint32_t* src = qg + (size_t)(qb*128 + r)*32 + c0;
        cp16(dst,      src);
        cp16(dst + 16, src + 4);
        cp16(dst + 32, src + 8);
        cp16(dst + 48, src + 12);
    }
    auto stageKV = [&](int kb, int s) {
        const int bk = K_OFF + s*64*VW3;
        const int bv = V_OFF + s*64*VW3;
        #pragma unroll
        for (int c = 0; c < 2; c++) {
            const int idx = tid*2 + c;
            const int r = idx >> 3, off = (idx & 7) * 4;
            cp16(smb + (uint32_t)(bk + r*VW3 + off) * 4,
                 kg + (size_t)(kb*64 + r)*32 + off);
            cp16(smb + (uint32_t)(bv + r*VW3 + off) * 4,
                 vtg + (size_t)r*(Tn/2) + kb*32 + off);
        }
    };
    stageKV(0, 0);
    CP_COMMIT();
    if (tid < 128) dsum[tid] = 0.f;

    float o[2][4][4];
    #pragma unroll
    for (int mt = 0; mt < 2; mt++)
        #pragma unroll
        for (int nt = 0; nt < 4; nt++)
            #pragma unroll
            for (int e = 0; e < 4; e++) o[mt][nt][e] = 0.f;
    float rs[2][2] = {{0.f,0.f},{0.f,0.f}};

    const int kbmax = 2*qb + 1;
    #pragma unroll 1
    for (int kb = 0; kb <= kbmax; kb++) {
        const int s = kb & 1;
        CP_WAIT0();
        __syncthreads();
        if (kb < kbmax) { stageKV(kb + 1, s ^ 1); CP_COMMIT(); }

        const uint32_t kbase = smb + (uint32_t)(K_OFF + s*64*VW3) * 4;
        const uint32_t vbase = smb + (uint32_t)(V_OFF + s*64*VW3) * 4;

        float sc[2][4][4];
        #pragma unroll
        for (int mt = 0; mt < 2; mt++)
            #pragma unroll
            for (int nt = 0; nt < 4; nt++)
                #pragma unroll
                for (int e = 0; e < 4; e++) sc[mt][nt][e] = 0.f;

        #pragma unroll
        for (int kt = 0; kt < 4; kt++) {
            uint32_t a[2][4];
            #pragma unroll
            for (int mt = 0; mt < 2; mt++)
                ldsm4(a[mt][0], a[mt][1], a[mt][2], a[mt][3],
                      smb + (uint32_t)((ib + mt*16 + lrow15)*VW3)*4 + lhi16 + kt*32);
            #pragma unroll
            for (int p = 0; p < 2; p++) {
                uint32_t b0, b1, b2, b3;
                ldsm4(b0, b1, b2, b3,
                      kbase + (uint32_t)((jd0 + p*16 + brow)*VW3)*4 + bchk16 + kt*32);
                #pragma unroll
                for (int mt = 0; mt < 2; mt++) {
                    mma_bf16(sc[mt][2*p+0], a[mt][0], a[mt][1], a[mt][2], a[mt][3], b0, b1);
                    mma_bf16(sc[mt][2*p+1], a[mt][0], a[mt][1], a[mt][2], a[mt][3], b2, b3);
                }
            }
        }

        const bool edge = (kb >= 2*qb);
        #pragma unroll
        for (int mt = 0; mt < 2; mt++) {
            #pragma unroll
            for (int nt = 0; nt < 4; nt++) {
                const int c = kb*64 + jd0 + nt*8 + 2*tg;
                float p0, p1, p2, p3;
                if (edge) {
                    const int r0g = qb*128 + ib + mt*16 + g;
                    const int r1g = r0g + 8;
                    p0 = (c   <= r0g) ? __expf(sc[mt][nt][0]) : 0.f;
                    p1 = (c+1 <= r0g) ? __expf(sc[mt][nt][1]) : 0.f;
                    p2 = (c   <= r1g) ? __expf(sc[mt][nt][2]) : 0.f;
                    p3 = (c+1 <= r1g) ? __expf(sc[mt][nt][3]) : 0.f;
                } else {
                    p0 = __expf(sc[mt][nt][0]); p1 = __expf(sc[mt][nt][1]);
                    p2 = __expf(sc[mt][nt][2]); p3 = __expf(sc[mt][nt][3]);
                }
                rs[mt][0] += p0 + p1;
                rs[mt][1] += p2 + p3;
                const int jw = (jd0 >> 1) + nt*4 + tg;
                smA[P_OFF + (ib + mt*16 + g    )*VW3 + jw] = pack_bf16(p0, p1);
                smA[P_OFF + (ib + mt*16 + g + 8)*VW3 + jw] = pack_bf16(p2, p3);
            }
        }
        __syncthreads();

        #pragma unroll
        for (int kt = 0; kt < 4; kt++) {
            uint32_t a[2][4];
            #pragma unroll
            for (int mt = 0; mt < 2; mt++)
                ldsm4(a[mt][0], a[mt][1], a[mt][2], a[mt][3],
                      smb + (uint32_t)(P_OFF*4) +
                      (uint32_t)((ib + mt*16 + lrow15)*VW3)*4 + lhi16 + kt*32);
            #pragma unroll
            for (int p = 0; p < 2; p++) {
                uint32_t b0, b1, b2, b3;
                ldsm4(b0, b1, b2, b3,
                      vbase + (uint32_t)((jd0 + p*16 + brow)*VW3)*4 + bchk16 + kt*32);
                #pragma unroll
                for (int mt = 0; mt < 2; mt++) {
                    mma_bf16(o[mt][2*p+0], a[mt][0], a[mt][1], a[mt][2], a[mt][3], b0, b1);
                    mma_bf16(o[mt][2*p+1], a[mt][0], a[mt][1], a[mt][2], a[mt][3], b2, b3);
                }
            }
        }
    }

    #pragma unroll
    for (int mt = 0; mt < 2; mt++) {
        rs[mt][0] += __shfl_xor_sync(0xffffffffu, rs[mt][0], 1);
        rs[mt][0] += __shfl_xor_sync(0xffffffffu, rs[mt][0], 2);
        rs[mt][1] += __shfl_xor_sync(0xffffffffu, rs[mt][1], 1);
        rs[mt][1] += __shfl_xor_sync(0xffffffffu, rs[mt][1], 2);
        if (tg == 0) {
            atomicAdd(&dsum[ib + mt*16 + g],     rs[mt][0]);
            atomicAdd(&dsum[ib + mt*16 + g + 8], rs[mt][1]);
        }
    }
    __syncthreads();

    uint32_t* yb = (uint32_t*)g_yb + ((size_t)(b*Tn + qb*128))*512 + h*32;
    #pragma unroll
    for (int mt = 0; mt < 2; mt++) {
        const float inv0 = 1.f / (dsum[ib + mt*16 + g]     + 1e-9f);
        const float inv1 = 1.f / (dsum[ib + mt*16 + g + 8] + 1e-9f);
        #pragma unroll
        for (int nt = 0; nt < 4; nt++) {
            const int cw = (jd0 >> 1) + nt*4 + tg;
            yb[(size_t)(ib + mt*16 + g    )*512 + cw] = pack_bf16(o[mt][nt][0]*inv0, o[mt][nt][1]*inv0);
            yb[(size_t)(ib + mt*16 + g + 8)*512 + cw] = pack_bf16(o[mt][nt][2]*inv1, o[mt][nt][3]*inv1);
        }
    }
}

// ============================================================
extern "C" void kernel_launch(void* const* d_in, const int* in_sizes, int n_in,
                              void* d_out, int out_size)
{
    (void)in_sizes; (void)n_in; (void)out_size;
    const float* x    = (const float*)d_in[0];
    // d_in[1] = attn_mask: deterministic causal, not needed
    const float* Wp   = (const float*)d_in[2];
    const float* bp   = (const float*)d_in[3];
    const float* Wo   = (const float*)d_in[4];
    const float* bo   = (const float*)d_in[5];
    const float* gam  = (const float*)d_in[6];
    const float* bet  = (const float*)d_in[7];
    float* out = (float*)d_out;

    const int SMEM_G = 4 * STG_W * 4;   // 49152 B
    cudaFuncSetAttribute(gemm_mma3<N_QKV, true>,
                         cudaFuncAttributeMaxDynamicSharedMemorySize, SMEM_G);
    cudaFuncSetAttribute(gemm_mma3<Dn, false>,
                         cudaFuncAttributeMaxDynamicSharedMemorySize, SMEM_G);
    const int SMEM_A3 = ATT3_W * 4;     // 73728 B
    cudaFuncSetAttribute(attn_v3,
                         cudaFuncAttributeMaxDynamicSharedMemorySize, SMEM_A3);

    prep_all<<<2048 + 96*32 + 32*32 + 1, 256>>>(x, Wp, Wo);

    gemm_mma3<N_QKV, true><<<dim3(N_QKV/128, M_TOT/128), 256, SMEM_G>>>(
        bp, nullptr, nullptr, nullptr, nullptr);

    attn_v3<<<dim3(Tn/128, Hn, Bn), 256, SMEM_A3>>>();

    gemm_mma3<Dn, false><<<dim3(Dn/128, M_TOT/128), 256, SMEM_G>>>(
        bo, x, gam, bet, out);
}

// round 13
// speedup vs baseline: 1.4810x; 1.4810x over previous
#include <cuda_runtime.h>
#include <cuda_bf16.h>
#include <math.h>
#include <stdint.h>

#define Bn  2
#define Tn  2048
#define Dn  1024
#define Hn  16
#define HDn 64
#define M_TOT 4096
#define N_QKV 3072

// -------- scratch (device globals: allocation-free) --------
__device__ __nv_bfloat16 g_q[(size_t)Bn*Hn*Tn*HDn];           // [b,h][t][d]
__device__ __nv_bfloat16 g_k[(size_t)Bn*Hn*Tn*HDn];           // [b,h][t][d]
__device__ __nv_bfloat16 g_vt[(size_t)Bn*Hn*HDn*Tn];          // [b,h][d][t]
__device__ __nv_bfloat16 g_yb[(size_t)M_TOT*Dn];              // attention out bf16
__device__ __nv_bfloat16 g_xb[(size_t)M_TOT*Dn];              // x bf16
__device__ __nv_bfloat16 g_wpt[(size_t)N_QKV*Dn];             // W_proj^T bf16 [N][K]
__device__ __nv_bfloat16 g_wot[(size_t)Dn*Dn];                // W_out^T  bf16 [N][K]
__device__ float g_z[(size_t)M_TOT*Dn];

// ---------------- helpers ----------------
__device__ __forceinline__ uint32_t pack_bf16(float lo, float hi) {
    uint32_t r;
    asm("cvt.rn.bf16x2.f32 %0, %1, %2;" : "=r"(r) : "f"(hi), "f"(lo));
    return r;
}

__device__ __forceinline__ void mma_bf16(float d[4],
                                         uint32_t a0, uint32_t a1, uint32_t a2, uint32_t a3,
                                         uint32_t b0, uint32_t b1) {
    asm volatile(
        "mma.sync.aligned.m16n8k16.row.col.f32.bf16.bf16.f32 "
        "{%0,%1,%2,%3}, {%4,%5,%6,%7}, {%8,%9}, {%0,%1,%2,%3};\n"
        : "+f"(d[0]), "+f"(d[1]), "+f"(d[2]), "+f"(d[3])
        : "r"(a0), "r"(a1), "r"(a2), "r"(a3), "r"(b0), "r"(b1));
}

__device__ __forceinline__ void ldsm4(uint32_t& r0, uint32_t& r1,
                                      uint32_t& r2, uint32_t& r3, uint32_t addr) {
    asm volatile("ldmatrix.sync.aligned.m8n8.x4.shared.b16 {%0,%1,%2,%3}, [%4];"
                 : "=r"(r0), "=r"(r1), "=r"(r2), "=r"(r3) : "r"(addr));
}

__device__ __forceinline__ uint32_t smem_u32(const void* p) {
    uint32_t a;
    asm("{ .reg .u64 t; cvta.to.shared.u64 t, %1; cvt.u32.u64 %0, t; }"
        : "=r"(a) : "l"(p));
    return a;
}

__device__ __forceinline__ void cp16(uint32_t dst, const void* src) {
    asm volatile("cp.async.cg.shared.global [%0], [%1], 16;"
                 :: "r"(dst), "l"(src) : "memory");
}
#define CP_COMMIT() asm volatile("cp.async.commit_group;" ::: "memory")
#define CP_WAIT2()  asm volatile("cp.async.wait_group 2;" ::: "memory")
#define CP_WAIT0()  asm volatile("cp.async.wait_group 0;" ::: "memory")

// ============================================================
// prep_all: x->bf16, Wp^T, Wo^T — ONE kernel launch
// ============================================================
__device__ __forceinline__ void transpose_block(
    const float* __restrict__ W, uint32_t* __restrict__ Wt,
    int N, int n0, int k0, int tid, float (*tile)[33])
{
    const int tx = tid & 31, ty = tid >> 5;
    #pragma unroll
    for (int p = 0; p < 4; p++) {
        int r = ty + p * 8;
        tile[r][tx] = W[(size_t)(k0 + r) * N + n0 + tx];
    }
    __syncthreads();
    const int wx = tid & 15, wy = tid >> 4;
    #pragma unroll
    for (int p = 0; p < 2; p++) {
        int rowo = wy + p * 16;
        uint32_t wv = pack_bf16(tile[2*wx][rowo], tile[2*wx+1][rowo]);
        Wt[(((size_t)(n0 + rowo) * Dn + k0) >> 1) + wx] = wv;
    }
}

__global__ __launch_bounds__(256) void prep_all(
    const float* __restrict__ x, const float* __restrict__ Wp,
    const float* __restrict__ Wo)
{
    __shared__ float tile[32][33];
    const int id = blockIdx.x;
    const int tid = threadIdx.x;
    if (id < 2048) {
        size_t i = ((size_t)id * 256 + tid) * 8;
        float4 a = *(const float4*)(x + i);
        float4 b = *(const float4*)(x + i + 4);
        uint4 o;
        o.x = pack_bf16(a.x, a.y); o.y = pack_bf16(a.z, a.w);
        o.z = pack_bf16(b.x, b.y); o.w = pack_bf16(b.z, b.w);
        *(uint4*)((uint32_t*)g_xb + (i >> 1)) = o;
    } else if (id < 2048 + 96*32) {
        const int idx = id - 2048;
        transpose_block(Wp, (uint32_t*)g_wpt, N_QKV,
                        (idx % 96) * 32, (idx / 96) * 32, tid, tile);
    } else {
        const int idx = id - (2048 + 96*32);
        transpose_block(Wo, (uint32_t*)g_wot, Dn,
                        (idx % 32) * 32, (idx / 32) * 32, tid, tile);
    }
}

// ============================================================
// bf16 HMMA GEMM: CTA 128x128, 256 thr, 2 CTAs/SM, 4-stage cp.async,
// one barrier per k16, B-fragment LDSMs hoisted ahead of MMAs.
// ============================================================
#define RSW 12                       // row stride words (48 B)
#define AST_W (128*RSW)              // 1536
#define STG_W (2*AST_W)              // 3072 words = 12 KB

template <int ND, bool IS_QKV>
__global__ __launch_bounds__(256, 2) void gemm_mma3(
    const float* __restrict__ bias, const float* __restrict__ Xres)
{
    extern __shared__ __align__(16) uint32_t sm3[];   // 4 * STG_W

    const int tid = threadIdx.x, lane = tid & 31, warp = tid >> 5;
    const int g = lane >> 2, tg = lane & 3;
    const int wm = (warp & 3) * 32;
    const int wn = (warp >> 2) * 64;
    const int m0 = blockIdx.y * 128, n0 = blockIdx.x * 128;

    const uint32_t* Aimg = (const uint32_t*)(IS_QKV ? g_xb : g_yb);
    const uint32_t* Bimg = (const uint32_t*)(IS_QKV ? g_wpt : g_wot);

    const uint32_t smb = smem_u32(sm3);

    const uint32_t a_ld = (wm + (lane & 15)) * 48 + ((lane >> 4) & 1) * 16;
    const uint32_t b_ld = AST_W*4 +
        (wn + (lane & 7) + ((lane >> 4) & 1) * 8) * 48 + ((lane >> 3) & 1) * 16;

    const int srow = tid >> 1, sch = tid & 1;

    float acc[2][8][4];
    #pragma unroll
    for (int i = 0; i < 2; i++)
        #pragma unroll
        for (int j = 0; j < 8; j++)
            #pragma unroll
            for (int e = 0; e < 4; e++) acc[i][j][e] = 0.f;

    auto stagef = [&](int kt) {
        uint32_t* st = sm3 + (kt & 3) * STG_W;
        cp16(smem_u32(st + srow*RSW + sch*4),
             Aimg + (size_t)(m0 + srow) * (Dn/2) + kt*8 + sch*4);
        cp16(smem_u32(st + AST_W + srow*RSW + sch*4),
             Bimg + (size_t)(n0 + srow) * (Dn/2) + kt*8 + sch*4);
        CP_COMMIT();
    };

    stagef(0); stagef(1); stagef(2);

    #pragma unroll 1
    for (int kt = 0; kt < 64; kt++) {
        if (kt <= 60) { CP_WAIT2(); } else { CP_WAIT0(); }
        __syncthreads();
        if (kt + 3 < 64) stagef(kt + 3);

        const uint32_t sb = smb + (kt & 3) * (STG_W * 4);

        uint32_t a[2][4], bfr[4][4];
        #pragma unroll
        for (int mt = 0; mt < 2; mt++)
            ldsm4(a[mt][0], a[mt][1], a[mt][2], a[mt][3], sb + a_ld + mt*768);
        #pragma unroll
        for (int nb = 0; nb < 4; nb++)
            ldsm4(bfr[nb][0], bfr[nb][1], bfr[nb][2], bfr[nb][3], sb + b_ld + nb*768);

        #pragma unroll
        for (int nb = 0; nb < 4; nb++) {
            #pragma unroll
            for (int mt = 0; mt < 2; mt++) {
                mma_bf16(acc[mt][nb*2+0], a[mt][0], a[mt][1], a[mt][2], a[mt][3],
                         bfr[nb][0], bfr[nb][1]);
                mma_bf16(acc[mt][nb*2+1], a[mt][0], a[mt][1], a[mt][2], a[mt][3],
                         bfr[nb][2], bfr[nb][3]);
            }
        }
    }

    const int ncb = n0 + wn;
    float2 bi[8];
    #pragma unroll
    for (int nt = 0; nt < 8; nt++)
        bi[nt] = *(const float2*)(bias + ncb + nt*8 + 2*tg);

    if (IS_QKV) {
        const int which = ncb >> 10;
        const int h = (ncb >> 6) & 15;
        if (which == 2) {
            const int dbase = ncb & 63;
            #pragma unroll
            for (int mt = 0; mt < 2; mt++) {
                #pragma unroll
                for (int hf = 0; hf < 2; hf++) {
                    const int m = m0 + wm + mt*16 + g + hf*8;
                    const int bb = m >> 11, t = m & 2047;
                    __nv_bfloat16* vt = g_vt + ((size_t)(bb*Hn + h) * 64) * Tn + t;
                    #pragma unroll
                    for (int nt = 0; nt < 8; nt++) {
                        const int d = dbase + nt*8 + 2*tg;
                        vt[(size_t)d*Tn]     = __float2bfloat16_rn(acc[mt][nt][hf*2+0] + bi[nt].x);
                        vt[(size_t)(d+1)*Tn] = __float2bfloat16_rn(acc[mt][nt][hf*2+1] + bi[nt].y);
                    }
                }
            }
        } else {
            const float scale = (which == 0) ? 0.125f : 1.f;
            uint32_t* base = (which == 0) ? (uint32_t*)g_q : (uint32_t*)g_k;
            #pragma unroll
            for (int mt = 0; mt < 2; mt++) {
                #pragma unroll
                for (int hf = 0; hf < 2; hf++) {
                    const int m = m0 + wm + mt*16 + g + hf*8;
                    const int b = m >> 11, t = m & 2047;
                    uint32_t* dst = base + ((size_t)(b*Hn + h)*Tn + t) * 32;
                    #pragma unroll
                    for (int nt = 0; nt < 8; nt++)
                        dst[nt*4 + tg] = pack_bf16(
                            (acc[mt][nt][hf*2+0] + bi[nt].x) * scale,
                            (acc[mt][nt][hf*2+1] + bi[nt].y) * scale);
                }
            }
        }
    } else {
        #pragma unroll
        for (int mt = 0; mt < 2; mt++) {
            #pragma unroll
            for (int hf = 0; hf < 2; hf++) {
                const int m = m0 + wm + mt*16 + g + hf*8;
                const float* xr = Xres + (size_t)m * Dn + ncb;
                float* zr = g_z + (size_t)m * Dn + ncb;
                #pragma unroll
                for (int nt = 0; nt < 8; nt++) {
                    const int off = nt*8 + 2*tg;
                    float2 xv = *(const float2*)(xr + off);
                    float2 o;
                    o.x = acc[mt][nt][hf*2+0] + bi[nt].x + xv.x;
                    o.y = acc[mt][nt][hf*2+1] + bi[nt].y + xv.y;
                    *(float2*)(zr + off) = o;
                }
            }
        }
    }
}

// ============================================================
// Causal attention v3 (R11, unchanged)
// ============================================================
#define VW3 36                         // row stride in words (144 B)
#define P_OFF (128*VW3)
#define K_OFF (2*128*VW3)
#define V_OFF (K_OFF + 2*64*VW3)
#define ATT3_W (V_OFF + 2*64*VW3)      // 18432 words = 73728 B

__global__ __launch_bounds__(256, 2) void attn_v3()
{
    extern __shared__ __align__(16) uint32_t smA[];
    __shared__ float dsum[128];

    const int qb = (Tn/128 - 1) - blockIdx.x;
    const int h = blockIdx.y, b = blockIdx.z;
    const int tid = threadIdx.x, lane = tid & 31, warp = tid >> 5;
    const int g = lane >> 2, tg = lane & 3;
    const int band = warp >> 1, half = warp & 1;
    const int ib  = band * 32;
    const int jd0 = half * 32;

    const size_t headw = ((size_t)(b*Hn + h)) * Tn * 32;
    const uint32_t* qg  = (const uint32_t*)g_q + headw;
    const uint32_t* kg  = (const uint32_t*)g_k + headw;
    const uint32_t* vtg = (const uint32_t*)g_vt + (size_t)(b*Hn + h) * 64 * (Tn/2);

    const uint32_t smb = smem_u32(smA);

    const int lrow15 = lane & 15;
    const int lhi16  = ((lane >> 4) & 1) * 16;
    const int brow   = (lane & 7) + ((lane >> 4) & 1) * 8;
    const int bchk16 = ((lane >> 3) & 1) * 16;

    {
        const int r = tid >> 1, c0 = (tid & 1) * 16;
        const uint32_t dst = smb + (uint32_t)(r*VW3 + c0) * 4;
        const uint32_t* src = qg + (size_t)(qb*128 + r)*32 + c0;
        cp16(dst,      src);
        cp16(dst + 16, src + 4);
        cp16(dst + 32, src + 8);
        cp16(dst + 48, src + 12);
    }
    auto stageKV = [&](int kb, int s) {
        const int bk = K_OFF + s*64*VW3;
        const int bv = V_OFF + s*64*VW3;
        #pragma unroll
        for (int c = 0; c < 2; c++) {
            const int idx = tid*2 + c;
            const int r = idx >> 3, off = (idx & 7) * 4;
            cp16(smb + (uint32_t)(bk + r*VW3 + off) * 4,
                 kg + (size_t)(kb*64 + r)*32 + off);
            cp16(smb + (uint32_t)(bv + r*VW3 + off) * 4,
                 vtg + (size_t)r*(Tn/2) + kb*32 + off);
        }
    };
    stageKV(0, 0);
    CP_COMMIT();
    if (tid < 128) dsum[tid] = 0.f;

    float o[2][4][4];
    #pragma unroll
    for (int mt = 0; mt < 2; mt++)
        #pragma unroll
        for (int nt = 0; nt < 4; nt++)
            #pragma unroll
            for (int e = 0; e < 4; e++) o[mt][nt][e] = 0.f;
    float rs[2][2] = {{0.f,0.f},{0.f,0.f}};

    const int kbmax = 2*qb + 1;
    #pragma unroll 1
    for (int kb = 0; kb <= kbmax; kb++) {
        const int s = kb & 1;
        CP_WAIT0();
        __syncthreads();
        if (kb < kbmax) { stageKV(kb + 1, s ^ 1); CP_COMMIT(); }

        const uint32_t kbase = smb + (uint32_t)(K_OFF + s*64*VW3) * 4;
        const uint32_t vbase = smb + (uint32_t)(V_OFF + s*64*VW3) * 4;

        float sc[2][4][4];
        #pragma unroll
        for (int mt = 0; mt < 2; mt++)
            #pragma unroll
            for (int nt = 0; nt < 4; nt++)
                #pragma unroll
                for (int e = 0; e < 4; e++) sc[mt][nt][e] = 0.f;

        #pragma unroll
        for (int kt = 0; kt < 4; kt++) {
            uint32_t a[2][4];
            #pragma unroll
            for (int mt = 0; mt < 2; mt++)
                ldsm4(a[mt][0], a[mt][1], a[mt][2], a[mt][3],
                      smb + (uint32_t)((ib + mt*16 + lrow15)*VW3)*4 + lhi16 + kt*32);
            #pragma unroll
            for (int p = 0; p < 2; p++) {
                uint32_t b0, b1, b2, b3;
                ldsm4(b0, b1, b2, b3,
                      kbase + (uint32_t)((jd0 + p*16 + brow)*VW3)*4 + bchk16 + kt*32);
                #pragma unroll
                for (int mt = 0; mt < 2; mt++) {
                    mma_bf16(sc[mt][2*p+0], a[mt][0], a[mt][1], a[mt][2], a[mt][3], b0, b1);
                    mma_bf16(sc[mt][2*p+1], a[mt][0], a[mt][1], a[mt][2], a[mt][3], b2, b3);
                }
            }
        }

        const bool edge = (kb >= 2*qb);
        #pragma unroll
        for (int mt = 0; mt < 2; mt++) {
            #pragma unroll
            for (int nt = 0; nt < 4; nt++) {
                const int c = kb*64 + jd0 + nt*8 + 2*tg;
                float p0, p1, p2, p3;
                if (edge) {
                    const int r0g = qb*128 + ib + mt*16 + g;
                    const int r1g = r0g + 8;
                    p0 = (c   <= r0g) ? __expf(sc[mt][nt][0]) : 0.f;
                    p1 = (c+1 <= r0g) ? __expf(sc[mt][nt][1]) : 0.f;
                    p2 = (c   <= r1g) ? __expf(sc[mt][nt][2]) : 0.f;
                    p3 = (c+1 <= r1g) ? __expf(sc[mt][nt][3]) : 0.f;
                } else {
                    p0 = __expf(sc[mt][nt][0]); p1 = __expf(sc[mt][nt][1]);
                    p2 = __expf(sc[mt][nt][2]); p3 = __expf(sc[mt][nt][3]);
                }
                rs[mt][0] += p0 + p1;
                rs[mt][1] += p2 + p3;
                const int jw = (jd0 >> 1) + nt*4 + tg;
                smA[P_OFF + (ib + mt*16 + g    )*VW3 + jw] = pack_bf16(p0, p1);
                smA[P_OFF + (ib + mt*16 + g + 8)*VW3 + jw] = pack_bf16(p2, p3);
            }
        }
        __syncthreads();

        #pragma unroll
        for (int kt = 0; kt < 4; kt++) {
            uint32_t a[2][4];
            #pragma unroll
            for (int mt = 0; mt < 2; mt++)
                ldsm4(a[mt][0], a[mt][1], a[mt][2], a[mt][3],
                      smb + (uint32_t)(P_OFF*4) +
                      (uint32_t)((ib + mt*16 + lrow15)*VW3)*4 + lhi16 + kt*32);
            #pragma unroll
            for (int p = 0; p < 2; p++) {
                uint32_t b0, b1, b2, b3;
                ldsm4(b0, b1, b2, b3,
                      vbase + (uint32_t)((jd0 + p*16 + brow)*VW3)*4 + bchk16 + kt*32);
                #pragma unroll
                for (int mt = 0; mt < 2; mt++) {
                    mma_bf16(o[mt][2*p+0], a[mt][0], a[mt][1], a[mt][2], a[mt][3], b0, b1);
                    mma_bf16(o[mt][2*p+1], a[mt][0], a[mt][1], a[mt][2], a[mt][3], b2, b3);
                }
            }
        }
    }

    #pragma unroll
    for (int mt = 0; mt < 2; mt++) {
        rs[mt][0] += __shfl_xor_sync(0xffffffffu, rs[mt][0], 1);
        rs[mt][0] += __shfl_xor_sync(0xffffffffu, rs[mt][0], 2);
        rs[mt][1] += __shfl_xor_sync(0xffffffffu, rs[mt][1], 1);
        rs[mt][1] += __shfl_xor_sync(0xffffffffu, rs[mt][1], 2);
        if (tg == 0) {
            atomicAdd(&dsum[ib + mt*16 + g],     rs[mt][0]);
            atomicAdd(&dsum[ib + mt*16 + g + 8], rs[mt][1]);
        }
    }
    __syncthreads();

    uint32_t* yb = (uint32_t*)g_yb + ((size_t)(b*Tn + qb*128))*512 + h*32;
    #pragma unroll
    for (int mt = 0; mt < 2; mt++) {
        const float inv0 = 1.f / (dsum[ib + mt*16 + g]     + 1e-9f);
        const float inv1 = 1.f / (dsum[ib + mt*16 + g + 8] + 1e-9f);
        #pragma unroll
        for (int nt = 0; nt < 4; nt++) {
            const int cw = (jd0 >> 1) + nt*4 + tg;
            yb[(size_t)(ib + mt*16 + g    )*512 + cw] = pack_bf16(o[mt][nt][0]*inv0, o[mt][nt][1]*inv0);
            yb[(size_t)(ib + mt*16 + g + 8)*512 + cw] = pack_bf16(o[mt][nt][2]*inv1, o[mt][nt][3]*inv1);
        }
    }
}

// ============================================================
// LayerNorm (R11 dedicated kernel — fast, massively parallel)
// ============================================================
__global__ __launch_bounds__(256) void ln_kernel(
    const float* __restrict__ gamma, const float* __restrict__ beta,
    float* __restrict__ out)
{
    int row = blockIdx.x;
    int tid = threadIdx.x;
    const float* z = g_z + (size_t)row * Dn + tid*4;
    float4 v = *(const float4*)z;
    float s  = v.x + v.y + v.z + v.w;
    float ss = v.x*v.x + v.y*v.y + v.z*v.z + v.w*v.w;

    #pragma unroll
    for (int off = 16; off; off >>= 1) {
        s  += __shfl_xor_sync(0xffffffffu, s,  off);
        ss += __shfl_xor_sync(0xffffffffu, ss, off);
    }

    __shared__ float rsm[8], rss[8];
    __shared__ float smu, srstd;
    int wid = tid >> 5, lane = tid & 31;
    if (lane == 0) { rsm[wid] = s; rss[wid] = ss; }
    __syncthreads();
    if (tid == 0) {
        float S = 0.f, SS = 0.f;
        #pragma unroll
        for (int w = 0; w < 8; w++) { S += rsm[w]; SS += rss[w]; }
        float mu  = S * (1.f / Dn);
        float var = SS * (1.f / Dn) - mu * mu;
        smu = mu;
        srstd = rsqrtf(var + 1e-5f);
    }
    __syncthreads();
    float mu = smu, rstd = srstd;

    float4 g4 = *(const float4*)(gamma + tid*4);
    float4 b4 = *(const float4*)(beta  + tid*4);
    float4 o;
    o.x = (v.x - mu)*rstd*g4.x + b4.x;
    o.y = (v.y - mu)*rstd*g4.y + b4.y;
    o.z = (v.z - mu)*rstd*g4.z + b4.z;
    o.w = (v.w - mu)*rstd*g4.w + b4.w;
    *(float4*)(out + (size_t)row * Dn + tid*4) = o;
}

// ============================================================
extern "C" void kernel_launch(void* const* d_in, const int* in_sizes, int n_in,
                              void* d_out, int out_size)
{
    (void)in_sizes; (void)n_in; (void)out_size;
    const float* x    = (const float*)d_in[0];
    // d_in[1] = attn_mask: deterministic causal, not needed
    const float* Wp   = (const float*)d_in[2];
    const float* bp   = (const float*)d_in[3];
    const float* Wo   = (const float*)d_in[4];
    const float* bo   = (const float*)d_in[5];
    const float* gam  = (const float*)d_in[6];
    const float* bet  = (const float*)d_in[7];
    float* out = (float*)d_out;

    const int SMEM_G = 4 * STG_W * 4;   // 49152 B
    cudaFuncSetAttribute(gemm_mma3<N_QKV, true>,
                         cudaFuncAttributeMaxDynamicSharedMemorySize, SMEM_G);
    cudaFuncSetAttribute(gemm_mma3<Dn, false>,
                         cudaFuncAttributeMaxDynamicSharedMemorySize, SMEM_G);
    const int SMEM_A3 = ATT3_W * 4;     // 73728 B
    cudaFuncSetAttribute(attn_v3,
                         cudaFuncAttributeMaxDynamicSharedMemorySize, SMEM_A3);

    prep_all<<<2048 + 96*32 + 32*32, 256>>>(x, Wp, Wo);

    gemm_mma3<N_QKV, true><<<dim3(N_QKV/128, M_TOT/128), 256, SMEM_G>>>(bp, nullptr);

    attn_v3<<<dim3(Tn/128, Hn, Bn), 256, SMEM_A3>>>();

    gemm_mma3<Dn, false><<<dim3(Dn/128, M_TOT/128), 256, SMEM_G>>>(bo, x);

    ln_kernel<<<M_TOT, 256>>>(gam, bet, out);
}

// round 15
// speedup vs baseline: 1.4872x; 1.0042x over previous
#include <cuda_runtime.h>
#include <cuda_bf16.h>
#include <math.h>
#include <stdint.h>

#define Bn  2
#define Tn  2048
#define Dn  1024
#define Hn  16
#define HDn 64
#define M_TOT 4096
#define N_QKV 3072

// -------- scratch (device globals: allocation-free) --------
__device__ __nv_bfloat16 g_q[(size_t)Bn*Hn*Tn*HDn];           // [b,h][t][d]
__device__ __nv_bfloat16 g_k[(size_t)Bn*Hn*Tn*HDn];           // [b,h][t][d]
__device__ __nv_bfloat16 g_vt[(size_t)Bn*Hn*HDn*Tn];          // [b,h][d][t]
__device__ __nv_bfloat16 g_yb[(size_t)M_TOT*Dn];              // attention out bf16
__device__ __nv_bfloat16 g_xb[(size_t)M_TOT*Dn];              // x bf16
__device__ __nv_bfloat16 g_wpt[(size_t)N_QKV*Dn];             // W_proj^T bf16 [N][K]
__device__ __nv_bfloat16 g_wot[(size_t)Dn*Dn];                // W_out^T  bf16 [N][K]
__device__ float g_z[(size_t)M_TOT*Dn];

// ---------------- helpers ----------------
__device__ __forceinline__ uint32_t pack_bf16(float lo, float hi) {
    uint32_t r;
    asm("cvt.rn.bf16x2.f32 %0, %1, %2;" : "=r"(r) : "f"(hi), "f"(lo));
    return r;
}

__device__ __forceinline__ void mma_bf16(float d[4],
                                         uint32_t a0, uint32_t a1, uint32_t a2, uint32_t a3,
                                         uint32_t b0, uint32_t b1) {
    asm volatile(
        "mma.sync.aligned.m16n8k16.row.col.f32.bf16.bf16.f32 "
        "{%0,%1,%2,%3}, {%4,%5,%6,%7}, {%8,%9}, {%0,%1,%2,%3};\n"
        : "+f"(d[0]), "+f"(d[1]), "+f"(d[2]), "+f"(d[3])
        : "r"(a0), "r"(a1), "r"(a2), "r"(a3), "r"(b0), "r"(b1));
}

__device__ __forceinline__ void ldsm4(uint32_t& r0, uint32_t& r1,
                                      uint32_t& r2, uint32_t& r3, uint32_t addr) {
    asm volatile("ldmatrix.sync.aligned.m8n8.x4.shared.b16 {%0,%1,%2,%3}, [%4];"
                 : "=r"(r0), "=r"(r1), "=r"(r2), "=r"(r3) : "r"(addr));
}

__device__ __forceinline__ uint32_t smem_u32(const void* p) {
    uint32_t a;
    asm("{ .reg .u64 t; cvta.to.shared.u64 t, %1; cvt.u32.u64 %0, t; }"
        : "=r"(a) : "l"(p));
    return a;
}

__device__ __forceinline__ void cp16(uint32_t dst, const void* src) {
    asm volatile("cp.async.cg.shared.global [%0], [%1], 16;"
                 :: "r"(dst), "l"(src) : "memory");
}
#define CP_COMMIT() asm volatile("cp.async.commit_group;" ::: "memory")
#define CP_WAIT1()  asm volatile("cp.async.wait_group 1;" ::: "memory")
#define CP_WAIT0()  asm volatile("cp.async.wait_group 0;" ::: "memory")

// ============================================================
// prep_all: x->bf16, Wp^T, Wo^T — ONE kernel launch
// ============================================================
__device__ __forceinline__ void transpose_block(
    const float* __restrict__ W, uint32_t* __restrict__ Wt,
    int N, int n0, int k0, int tid, float (*tile)[33])
{
    const int tx = tid & 31, ty = tid >> 5;
    #pragma unroll
    for (int p = 0; p < 4; p++) {
        int r = ty + p * 8;
        tile[r][tx] = W[(size_t)(k0 + r) * N + n0 + tx];
    }
    __syncthreads();
    const int wx = tid & 15, wy = tid >> 4;
    #pragma unroll
    for (int p = 0; p < 2; p++) {
        int rowo = wy + p * 16;
        uint32_t wv = pack_bf16(tile[2*wx][rowo], tile[2*wx+1][rowo]);
        Wt[(((size_t)(n0 + rowo) * Dn + k0) >> 1) + wx] = wv;
    }
}

__global__ __launch_bounds__(256) void prep_all(
    const float* __restrict__ x, const float* __restrict__ Wp,
    const float* __restrict__ Wo)
{
    __shared__ float tile[32][33];
    const int id = blockIdx.x;
    const int tid = threadIdx.x;
    if (id < 2048) {
        size_t i = ((size_t)id * 256 + tid) * 8;
        float4 a = *(const float4*)(x + i);
        float4 b = *(const float4*)(x + i + 4);
        uint4 o;
        o.x = pack_bf16(a.x, a.y); o.y = pack_bf16(a.z, a.w);
        o.z = pack_bf16(b.x, b.y); o.w = pack_bf16(b.z, b.w);
        *(uint4*)((uint32_t*)g_xb + (i >> 1)) = o;
    } else if (id < 2048 + 96*32) {
        const int idx = id - 2048;
        transpose_block(Wp, (uint32_t*)g_wpt, N_QKV,
                        (idx % 96) * 32, (idx / 96) * 32, tid, tile);
    } else {
        const int idx = id - (2048 + 96*32);
        transpose_block(Wo, (uint32_t*)g_wot, Dn,
                        (idx % 32) * 32, (idx / 32) * 32, tid, tile);
    }
}

// ============================================================
// bf16 HMMA GEMM v5 (fixed): CTA 128x128, 256 thr, 2 CTAs/SM,
// BK=32 staged (2 k16 substeps / buffer), 3-stage cp.async ring,
// ONE barrier per 2 k16. Rows: 64B payload, 80B stride.
// ============================================================
#define RSW 20                       // row stride words (80 B)
#define AST_W (128*RSW)              // 2560
#define STG_W (2*AST_W)              // 5120 words = 20 KB

template <int ND, bool IS_QKV>
__global__ __launch_bounds__(256, 2) void gemm_mma5(
    const float* __restrict__ bias, const float* __restrict__ Xres)
{
    extern __shared__ __align__(16) uint32_t sm5[];   // 3 * STG_W

    const int tid = threadIdx.x, lane = tid & 31, warp = tid >> 5;
    const int g = lane >> 2, tg = lane & 3;
    const int wm = (warp & 3) * 32;
    const int wn = (warp >> 2) * 64;
    const int m0 = blockIdx.y * 128, n0 = blockIdx.x * 128;

    const uint32_t* Aimg = (const uint32_t*)(IS_QKV ? g_xb : g_yb);
    const uint32_t* Bimg = (const uint32_t*)(IS_QKV ? g_wpt : g_wot);

    const uint32_t smb = smem_u32(sm5);

    const uint32_t a_ld = (wm + (lane & 15)) * 80 + ((lane >> 4) & 1) * 16;
    const uint32_t b_ld = AST_W*4 +
        (wn + (lane & 7) + ((lane >> 4) & 1) * 8) * 80 + ((lane >> 3) & 1) * 16;

    float acc[2][8][4];
    #pragma unroll
    for (int i = 0; i < 2; i++)
        #pragma unroll
        for (int j = 0; j < 8; j++)
            #pragma unroll
            for (int e = 0; e < 4; e++) acc[i][j][e] = 0.f;

    auto stagef = [&](int kt) {       // kt counts 32-wide k blocks (0..31)
        uint32_t* st = sm5 + (kt % 3) * STG_W;
        #pragma unroll
        for (int p = 0; p < 4; p++) {
            const int idx = tid + p * 256;
            const int r = idx >> 2;          // 0..255
            const int c = (idx & 3) * 4;     // word chunk
            if (r < 128)
                cp16(smem_u32(st + r*RSW + c),
                     Aimg + (size_t)(m0 + r) * (Dn/2) + kt*16 + c);
            else
                cp16(smem_u32(st + AST_W + (r-128)*RSW + c),
                     Bimg + (size_t)(n0 + r - 128) * (Dn/2) + kt*16 + c);
        }
        CP_COMMIT();
    };

    stagef(0); stagef(1);

    #pragma unroll 1
    for (int kt = 0; kt < 32; kt++) {
        if (kt < 31) { CP_WAIT1(); } else { CP_WAIT0(); }
        __syncthreads();
        if (kt + 2 < 32) stagef(kt + 2);

        const uint32_t sb = smb + (uint32_t)(kt % 3) * (STG_W * 4);

        #pragma unroll
        for (int ks = 0; ks < 2; ks++) {
            const uint32_t ko = ks * 32;      // byte offset for this k16
            uint32_t a[2][4], bfr[4][4];
            #pragma unroll
            for (int mt = 0; mt < 2; mt++)
                ldsm4(a[mt][0], a[mt][1], a[mt][2], a[mt][3],
                      sb + a_ld + ko + mt*1280);
            #pragma unroll
            for (int nb = 0; nb < 4; nb++)
                ldsm4(bfr[nb][0], bfr[nb][1], bfr[nb][2], bfr[nb][3],
                      sb + b_ld + ko + nb*1280);      // FIX: 16 rows = 1280 B each

            #pragma unroll
            for (int nb = 0; nb < 4; nb++) {
                #pragma unroll
                for (int mt = 0; mt < 2; mt++) {
                    mma_bf16(acc[mt][nb*2+0], a[mt][0], a[mt][1], a[mt][2], a[mt][3],
                             bfr[nb][0], bfr[nb][1]);
                    mma_bf16(acc[mt][nb*2+1], a[mt][0], a[mt][1], a[mt][2], a[mt][3],
                             bfr[nb][2], bfr[nb][3]);
                }
            }
        }
    }

    const int ncb = n0 + wn;
    float2 bi[8];
    #pragma unroll
    for (int nt = 0; nt < 8; nt++)
        bi[nt] = *(const float2*)(bias + ncb + nt*8 + 2*tg);

    if (IS_QKV) {
        const int which = ncb >> 10;
        const int h = (ncb >> 6) & 15;
        if (which == 2) {
            const int dbase = ncb & 63;
            #pragma unroll
            for (int mt = 0; mt < 2; mt++) {
                #pragma unroll
                for (int hf = 0; hf < 2; hf++) {
                    const int m = m0 + wm + mt*16 + g + hf*8;
                    const int bb = m >> 11, t = m & 2047;
                    __nv_bfloat16* vt = g_vt + ((size_t)(bb*Hn + h) * 64) * Tn + t;
                    #pragma unroll
                    for (int nt = 0; nt < 8; nt++) {
                        const int d = dbase + nt*8 + 2*tg;
                        vt[(size_t)d*Tn]     = __float2bfloat16_rn(acc[mt][nt][hf*2+0] + bi[nt].x);
                        vt[(size_t)(d+1)*Tn] = __float2bfloat16_rn(acc[mt][nt][hf*2+1] + bi[nt].y);
                    }
                }
            }
        } else {
            const float scale = (which == 0) ? 0.125f : 1.f;
            uint32_t* base = (which == 0) ? (uint32_t*)g_q : (uint32_t*)g_k;
            #pragma unroll
            for (int mt = 0; mt < 2; mt++) {
                #pragma unroll
                for (int hf = 0; hf < 2; hf++) {
                    const int m = m0 + wm + mt*16 + g + hf*8;
                    const int b = m >> 11, t = m & 2047;
                    uint32_t* dst = base + ((size_t)(b*Hn + h)*Tn + t) * 32;
                    #pragma unroll
                    for (int nt = 0; nt < 8; nt++)
                        dst[nt*4 + tg] = pack_bf16(
                            (acc[mt][nt][hf*2+0] + bi[nt].x) * scale,
                            (acc[mt][nt][hf*2+1] + bi[nt].y) * scale);
                }
            }
        }
    } else {
        #pragma unroll
        for (int mt = 0; mt < 2; mt++) {
            #pragma unroll
            for (int hf = 0; hf < 2; hf++) {
                const int m = m0 + wm + mt*16 + g + hf*8;
                const float* xr = Xres + (size_t)m * Dn + ncb;
                float* zr = g_z + (size_t)m * Dn + ncb;
                #pragma unroll
                for (int nt = 0; nt < 8; nt++) {
                    const int off = nt*8 + 2*tg;
                    float2 xv = *(const float2*)(xr + off);
                    float2 o;
                    o.x = acc[mt][nt][hf*2+0] + bi[nt].x + xv.x;
                    o.y = acc[mt][nt][hf*2+1] + bi[nt].y + xv.y;
                    *(float2*)(zr + off) = o;
                }
            }
        }
    }
}

// ============================================================
// Causal attention v3 (R11/R13, unchanged)
// ============================================================
#define VW3 36                         // row stride in words (144 B)
#define P_OFF (128*VW3)
#define K_OFF (2*128*VW3)
#define V_OFF (K_OFF + 2*64*VW3)
#define ATT3_W (V_OFF + 2*64*VW3)      // 18432 words = 73728 B

__global__ __launch_bounds__(256, 2) void attn_v3()
{
    extern __shared__ __align__(16) uint32_t smA[];
    __shared__ float dsum[128];

    const int qb = (Tn/128 - 1) - blockIdx.x;
    const int h = blockIdx.y, b = blockIdx.z;
    const int tid = threadIdx.x, lane = tid & 31, warp = tid >> 5;
    const int g = lane >> 2, tg = lane & 3;
    const int band = warp >> 1, half = warp & 1;
    const int ib  = band * 32;
    const int jd0 = half * 32;

    const size_t headw = ((size_t)(b*Hn + h)) * Tn * 32;
    const uint32_t* qg  = (const uint32_t*)g_q + headw;
    const uint32_t* kg  = (const uint32_t*)g_k + headw;
    const uint32_t* vtg = (const uint32_t*)g_vt + (size_t)(b*Hn + h) * 64 * (Tn/2);

    const uint32_t smb = smem_u32(smA);

    const int lrow15 = lane & 15;
    const int lhi16  = ((lane >> 4) & 1) * 16;
    const int brow   = (lane & 7) + ((lane >> 4) & 1) * 8;
    const int bchk16 = ((lane >> 3) & 1) * 16;

    {
        const int r = tid >> 1, c0 = (tid & 1) * 16;
        const uint32_t dst = smb + (uint32_t)(r*VW3 + c0) * 4;
        const uint32_t* src = qg + (size_t)(qb*128 + r)*32 + c0;
        cp16(dst,      src);
        cp16(dst + 16, src + 4);
        cp16(dst + 32, src + 8);
        cp16(dst + 48, src + 12);
    }
    auto stageKV = [&](int kb, int s) {
        const int bk = K_OFF + s*64*VW3;
        const int bv = V_OFF + s*64*VW3;
        #pragma unroll
        for (int c = 0; c < 2; c++) {
            const int idx = tid*2 + c;
            const int r = idx >> 3, off = (idx & 7) * 4;
            cp16(smb + (uint32_t)(bk + r*VW3 + off) * 4,
                 kg + (size_t)(kb*64 + r)*32 + off);
            cp16(smb + (uint32_t)(bv + r*VW3 + off) * 4,
                 vtg + (size_t)r*(Tn/2) + kb*32 + off);
        }
    };
    stageKV(0, 0);
    CP_COMMIT();
    if (tid < 128) dsum[tid] = 0.f;

    float o[2][4][4];
    #pragma unroll
    for (int mt = 0; mt < 2; mt++)
        #pragma unroll
        for (int nt = 0; nt < 4; nt++)
            #pragma unroll
            for (int e = 0; e < 4; e++) o[mt][nt][e] = 0.f;
    float rs[2][2] = {{0.f,0.f},{0.f,0.f}};

    const int kbmax = 2*qb + 1;
    #pragma unroll 1
    for (int kb = 0; kb <= kbmax; kb++) {
        const int s = kb & 1;
        CP_WAIT0();
        __syncthreads();
        if (kb < kbmax) { stageKV(kb + 1, s ^ 1); CP_COMMIT(); }

        const uint32_t kbase = smb + (uint32_t)(K_OFF + s*64*VW3) * 4;
        const uint32_t vbase = smb + (uint32_t)(V_OFF + s*64*VW3) * 4;

        float sc[2][4][4];
        #pragma unroll
        for (int mt = 0; mt < 2; mt++)
            #pragma unroll
            for (int nt = 0; nt < 4; nt++)
                #pragma unroll
                for (int e = 0; e < 4; e++) sc[mt][nt][e] = 0.f;

        #pragma unroll
        for (int kt = 0; kt < 4; kt++) {
            uint32_t a[2][4];
            #pragma unroll
            for (int mt = 0; mt < 2; mt++)
                ldsm4(a[mt][0], a[mt][1], a[mt][2], a[mt][3],
                      smb + (uint32_t)((ib + mt*16 + lrow15)*VW3)*4 + lhi16 + kt*32);
            #pragma unroll
            for (int p = 0; p < 2; p++) {
                uint32_t b0, b1, b2, b3;
                ldsm4(b0, b1, b2, b3,
                      kbase + (uint32_t)((jd0 + p*16 + brow)*VW3)*4 + bchk16 + kt*32);
                #pragma unroll
                for (int mt = 0; mt < 2; mt++) {
                    mma_bf16(sc[mt][2*p+0], a[mt][0], a[mt][1], a[mt][2], a[mt][3], b0, b1);
                    mma_bf16(sc[mt][2*p+1], a[mt][0], a[mt][1], a[mt][2], a[mt][3], b2, b3);
                }
            }
        }

        const bool edge = (kb >= 2*qb);
        #pragma unroll
        for (int mt = 0; mt < 2; mt++) {
            #pragma unroll
            for (int nt = 0; nt < 4; nt++) {
                const int c = kb*64 + jd0 + nt*8 + 2*tg;
                float p0, p1, p2, p3;
                if (edge) {
                    const int r0g = qb*128 + ib + mt*16 + g;
                    const int r1g = r0g + 8;
                    p0 = (c   <= r0g) ? __expf(sc[mt][nt][0]) : 0.f;
                    p1 = (c+1 <= r0g) ? __expf(sc[mt][nt][1]) : 0.f;
                    p2 = (c   <= r1g) ? __expf(sc[mt][nt][2]) : 0.f;
                    p3 = (c+1 <= r1g) ? __expf(sc[mt][nt][3]) : 0.f;
                } else {
                    p0 = __expf(sc[mt][nt][0]); p1 = __expf(sc[mt][nt][1]);
                    p2 = __expf(sc[mt][nt][2]); p3 = __expf(sc[mt][nt][3]);
                }
                rs[mt][0] += p0 + p1;
                rs[mt][1] += p2 + p3;
                const int jw = (jd0 >> 1) + nt*4 + tg;
                smA[P_OFF + (ib + mt*16 + g    )*VW3 + jw] = pack_bf16(p0, p1);
                smA[P_OFF + (ib + mt*16 + g + 8)*VW3 + jw] = pack_bf16(p2, p3);
            }
        }
        __syncthreads();

        #pragma unroll
        for (int kt = 0; kt < 4; kt++) {
            uint32_t a[2][4];
            #pragma unroll
            for (int mt = 0; mt < 2; mt++)
                ldsm4(a[mt][0], a[mt][1], a[mt][2], a[mt][3],
                      smb + (uint32_t)(P_OFF*4) +
                      (uint32_t)((ib + mt*16 + lrow15)*VW3)*4 + lhi16 + kt*32);
            #pragma unroll
            for (int p = 0; p < 2; p++) {
                uint32_t b0, b1, b2, b3;
                ldsm4(b0, b1, b2, b3,
                      vbase + (uint32_t)((jd0 + p*16 + brow)*VW3)*4 + bchk16 + kt*32);
                #pragma unroll
                for (int mt = 0; mt < 2; mt++) {
                    mma_bf16(o[mt][2*p+0], a[mt][0], a[mt][1], a[mt][2], a[mt][3], b0, b1);
                    mma_bf16(o[mt][2*p+1], a[mt][0], a[mt][1], a[mt][2], a[mt][3], b2, b3);
                }
            }
        }
    }

    #pragma unroll
    for (int mt = 0; mt < 2; mt++) {
        rs[mt][0] += __shfl_xor_sync(0xffffffffu, rs[mt][0], 1);
        rs[mt][0] += __shfl_xor_sync(0xffffffffu, rs[mt][0], 2);
        rs[mt][1] += __shfl_xor_sync(0xffffffffu, rs[mt][1], 1);
        rs[mt][1] += __shfl_xor_sync(0xffffffffu, rs[mt][1], 2);
        if (tg == 0) {
            atomicAdd(&dsum[ib + mt*16 + g],     rs[mt][0]);
            atomicAdd(&dsum[ib + mt*16 + g + 8], rs[mt][1]);
        }
    }
    __syncthreads();

    uint32_t* yb = (uint32_t*)g_yb + ((size_t)(b*Tn + qb*128))*512 + h*32;
    #pragma unroll
    for (int mt = 0; mt < 2; mt++) {
        const float inv0 = 1.f / (dsum[ib + mt*16 + g]     + 1e-9f);
        const float inv1 = 1.f / (dsum[ib + mt*16 + g + 8] + 1e-9f);
        #pragma unroll
        for (int nt = 0; nt < 4; nt++) {
            const int cw = (jd0 >> 1) + nt*4 + tg;
            yb[(size_t)(ib + mt*16 + g    )*512 + cw] = pack_bf16(o[mt][nt][0]*inv0, o[mt][nt][1]*inv0);
            yb[(size_t)(ib + mt*16 + g + 8)*512 + cw] = pack_bf16(o[mt][nt][2]*inv1, o[mt][nt][3]*inv1);
        }
    }
}

// ============================================================
// LayerNorm (dedicated kernel)
// ============================================================
__global__ __launch_bounds__(256) void ln_kernel(
    const float* __restrict__ gamma, const float* __restrict__ beta,
    float* __restrict__ out)
{
    int row = blockIdx.x;
    int tid = threadIdx.x;
    const float* z = g_z + (size_t)row * Dn + tid*4;
    float4 v = *(const float4*)z;
    float s  = v.x + v.y + v.z + v.w;
    float ss = v.x*v.x + v.y*v.y + v.z*v.z + v.w*v.w;

    #pragma unroll
    for (int off = 16; off; off >>= 1) {
        s  += __shfl_xor_sync(0xffffffffu, s,  off);
        ss += __shfl_xor_sync(0xffffffffu, ss, off);
    }

    __shared__ float rsm[8], rss[8];
    __shared__ float smu, srstd;
    int wid = tid >> 5, lane = tid & 31;
    if (lane == 0) { rsm[wid] = s; rss[wid] = ss; }
    __syncthreads();
    if (tid == 0) {
        float S = 0.f, SS = 0.f;
        #pragma unroll
        for (int w = 0; w < 8; w++) { S += rsm[w]; SS += rss[w]; }
        float mu  = S * (1.f / Dn);
        float var = SS * (1.f / Dn) - mu * mu;
        smu = mu;
        srstd = rsqrtf(var + 1e-5f);
    }
    __syncthreads();
    float mu = smu, rstd = srstd;

    float4 g4 = *(const float4*)(gamma + tid*4);
    float4 b4 = *(const float4*)(beta  + tid*4);
    float4 o;
    o.x = (v.x - mu)*rstd*g4.x + b4.x;
    o.y = (v.y - mu)*rstd*g4.y + b4.y;
    o.z = (v.z - mu)*rstd*g4.z + b4.z;
    o.w = (v.w - mu)*rstd*g4.w + b4.w;
    *(float4*)(out + (size_t)row * Dn + tid*4) = o;
}

// ============================================================
extern "C" void kernel_launch(void* const* d_in, const int* in_sizes, int n_in,
                              void* d_out, int out_size)
{
    (void)in_sizes; (void)n_in; (void)out_size;
    const float* x    = (const float*)d_in[0];
    // d_in[1] = attn_mask: deterministic causal, not needed
    const float* Wp   = (const float*)d_in[2];
    const float* bp   = (const float*)d_in[3];
    const float* Wo   = (const float*)d_in[4];
    const float* bo   = (const float*)d_in[5];
    const float* gam  = (const float*)d_in[6];
    const float* bet  = (const float*)d_in[7];
    float* out = (float*)d_out;

    const int SMEM_G = 3 * STG_W * 4;   // 61440 B
    cudaFuncSetAttribute(gemm_mma5<N_QKV, true>,
                         cudaFuncAttributeMaxDynamicSharedMemorySize, SMEM_G);
    cudaFuncSetAttribute(gemm_mma5<Dn, false>,
                         cudaFuncAttributeMaxDynamicSharedMemorySize, SMEM_G);
    const int SMEM_A3 = ATT3_W * 4;     // 73728 B
    cudaFuncSetAttribute(attn_v3,
                         cudaFuncAttributeMaxDynamicSharedMemorySize, SMEM_A3);

    prep_all<<<2048 + 96*32 + 32*32, 256>>>(x, Wp, Wo);

    gemm_mma5<N_QKV, true><<<dim3(N_QKV/128, M_TOT/128), 256, SMEM_G>>>(bp, nullptr);

    attn_v3<<<dim3(Tn/128, Hn, Bn), 256, SMEM_A3>>>();

    gemm_mma5<Dn, false><<<dim3(Dn/128, M_TOT/128), 256, SMEM_G>>>(bo, x);

    ln_kernel<<<M_TOT, 256>>>(gam, bet, out);
}

// round 16
// speedup vs baseline: 1.6849x; 1.1330x over previous
#include <cuda_runtime.h>
#include <cuda_bf16.h>
#include <math.h>
#include <stdint.h>

#define Bn  2
#define Tn  2048
#define Dn  1024
#define Hn  16
#define HDn 64
#define M_TOT 4096
#define N_QKV 3072

// -------- scratch (device globals: allocation-free) --------
__device__ __nv_bfloat16 g_q[(size_t)Bn*Hn*Tn*HDn];           // [b,h][t][d]
__device__ __nv_bfloat16 g_k[(size_t)Bn*Hn*Tn*HDn];           // [b,h][t][d]
__device__ __nv_bfloat16 g_vt[(size_t)Bn*Hn*HDn*Tn];          // [b,h][d][t]
__device__ __nv_bfloat16 g_yb[(size_t)M_TOT*Dn];              // attention out bf16
__device__ __nv_bfloat16 g_xb[(size_t)M_TOT*Dn];              // x bf16
__device__ __nv_bfloat16 g_wpt[(size_t)N_QKV*Dn];             // W_proj^T bf16 [N][K]
__device__ __nv_bfloat16 g_wot[(size_t)Dn*Dn];                // W_out^T  bf16 [N][K]
__device__ float g_z[(size_t)M_TOT*Dn];

// ---------------- helpers ----------------
__device__ __forceinline__ uint32_t pack_bf16(float lo, float hi) {
    uint32_t r;
    asm("cvt.rn.bf16x2.f32 %0, %1, %2;" : "=r"(r) : "f"(hi), "f"(lo));
    return r;
}

__device__ __forceinline__ void mma_bf16(float d[4],
                                         uint32_t a0, uint32_t a1, uint32_t a2, uint32_t a3,
                                         uint32_t b0, uint32_t b1) {
    asm volatile(
        "mma.sync.aligned.m16n8k16.row.col.f32.bf16.bf16.f32 "
        "{%0,%1,%2,%3}, {%4,%5,%6,%7}, {%8,%9}, {%0,%1,%2,%3};\n"
        : "+f"(d[0]), "+f"(d[1]), "+f"(d[2]), "+f"(d[3])
        : "r"(a0), "r"(a1), "r"(a2), "r"(a3), "r"(b0), "r"(b1));
}

__device__ __forceinline__ void ldsm4(uint32_t& r0, uint32_t& r1,
                                      uint32_t& r2, uint32_t& r3, uint32_t addr) {
    asm volatile("ldmatrix.sync.aligned.m8n8.x4.shared.b16 {%0,%1,%2,%3}, [%4];"
                 : "=r"(r0), "=r"(r1), "=r"(r2), "=r"(r3) : "r"(addr));
}

__device__ __forceinline__ uint32_t smem_u32(const void* p) {
    uint32_t a;
    asm("{ .reg .u64 t; cvta.to.shared.u64 t, %1; cvt.u32.u64 %0, t; }"
        : "=r"(a) : "l"(p));
    return a;
}

__device__ __forceinline__ void cp16(uint32_t dst, const void* src) {
    asm volatile("cp.async.cg.shared.global [%0], [%1], 16;"
                 :: "r"(dst), "l"(src) : "memory");
}
#define CP_COMMIT() asm volatile("cp.async.commit_group;" ::: "memory")
#define CP_WAIT1()  asm volatile("cp.async.wait_group 1;" ::: "memory")
#define CP_WAIT0()  asm volatile("cp.async.wait_group 0;" ::: "memory")

// ============================================================
// prep_all: x->bf16, Wp^T, Wo^T — ONE kernel launch
// ============================================================
__device__ __forceinline__ void transpose_block(
    const float* __restrict__ W, uint32_t* __restrict__ Wt,
    int N, int n0, int k0, int tid, float (*tile)[33])
{
    const int tx = tid & 31, ty = tid >> 5;
    #pragma unroll
    for (int p = 0; p < 4; p++) {
        int r = ty + p * 8;
        tile[r][tx] = W[(size_t)(k0 + r) * N + n0 + tx];
    }
    __syncthreads();
    const int wx = tid & 15, wy = tid >> 4;
    #pragma unroll
    for (int p = 0; p < 2; p++) {
        int rowo = wy + p * 16;
        uint32_t wv = pack_bf16(tile[2*wx][rowo], tile[2*wx+1][rowo]);
        Wt[(((size_t)(n0 + rowo) * Dn + k0) >> 1) + wx] = wv;
    }
}

__global__ __launch_bounds__(256) void prep_all(
    const float* __restrict__ x, const float* __restrict__ Wp,
    const float* __restrict__ Wo)
{
    __shared__ float tile[32][33];
    const int id = blockIdx.x;
    const int tid = threadIdx.x;
    if (id < 2048) {
        size_t i = ((size_t)id * 256 + tid) * 8;
        float4 a = *(const float4*)(x + i);
        float4 b = *(const float4*)(x + i + 4);
        uint4 o;
        o.x = pack_bf16(a.x, a.y); o.y = pack_bf16(a.z, a.w);
        o.z = pack_bf16(b.x, b.y); o.w = pack_bf16(b.z, b.w);
        *(uint4*)((uint32_t*)g_xb + (i >> 1)) = o;
    } else if (id < 2048 + 96*32) {
        const int idx = id - 2048;
        transpose_block(Wp, (uint32_t*)g_wpt, N_QKV,
                        (idx % 96) * 32, (idx / 96) * 32, tid, tile);
    } else {
        const int idx = id - (2048 + 96*32);
        transpose_block(Wo, (uint32_t*)g_wot, Dn,
                        (idx % 32) * 32, (idx / 32) * 32, tid, tile);
    }
}

// ============================================================
// bf16 HMMA GEMM v5 (converged config, unchanged from R15)
// ============================================================
#define RSW 20                       // row stride words (80 B)
#define AST_W (128*RSW)              // 2560
#define STG_W (2*AST_W)              // 5120 words = 20 KB

template <int ND, bool IS_QKV>
__global__ __launch_bounds__(256, 2) void gemm_mma5(
    const float* __restrict__ bias, const float* __restrict__ Xres)
{
    extern __shared__ __align__(16) uint32_t sm5[];   // 3 * STG_W

    const int tid = threadIdx.x, lane = tid & 31, warp = tid >> 5;
    const int g = lane >> 2, tg = lane & 3;
    const int wm = (warp & 3) * 32;
    const int wn = (warp >> 2) * 64;
    const int m0 = blockIdx.y * 128, n0 = blockIdx.x * 128;

    const uint32_t* Aimg = (const uint32_t*)(IS_QKV ? g_xb : g_yb);
    const uint32_t* Bimg = (const uint32_t*)(IS_QKV ? g_wpt : g_wot);

    const uint32_t smb = smem_u32(sm5);

    const uint32_t a_ld = (wm + (lane & 15)) * 80 + ((lane >> 4) & 1) * 16;
    const uint32_t b_ld = AST_W*4 +
        (wn + (lane & 7) + ((lane >> 4) & 1) * 8) * 80 + ((lane >> 3) & 1) * 16;

    float acc[2][8][4];
    #pragma unroll
    for (int i = 0; i < 2; i++)
        #pragma unroll
        for (int j = 0; j < 8; j++)
            #pragma unroll
            for (int e = 0; e < 4; e++) acc[i][j][e] = 0.f;

    auto stagef = [&](int kt) {
        uint32_t* st = sm5 + (kt % 3) * STG_W;
        #pragma unroll
        for (int p = 0; p < 4; p++) {
            const int idx = tid + p * 256;
            const int r = idx >> 2;
            const int c = (idx & 3) * 4;
            if (r < 128)
                cp16(smem_u32(st + r*RSW + c),
                     Aimg + (size_t)(m0 + r) * (Dn/2) + kt*16 + c);
            else
                cp16(smem_u32(st + AST_W + (r-128)*RSW + c),
                     Bimg + (size_t)(n0 + r - 128) * (Dn/2) + kt*16 + c);
        }
        CP_COMMIT();
    };

    stagef(0); stagef(1);

    #pragma unroll 1
    for (int kt = 0; kt < 32; kt++) {
        if (kt < 31) { CP_WAIT1(); } else { CP_WAIT0(); }
        __syncthreads();
        if (kt + 2 < 32) stagef(kt + 2);

        const uint32_t sb = smb + (uint32_t)(kt % 3) * (STG_W * 4);

        #pragma unroll
        for (int ks = 0; ks < 2; ks++) {
            const uint32_t ko = ks * 32;
            uint32_t a[2][4], bfr[4][4];
            #pragma unroll
            for (int mt = 0; mt < 2; mt++)
                ldsm4(a[mt][0], a[mt][1], a[mt][2], a[mt][3],
                      sb + a_ld + ko + mt*1280);
            #pragma unroll
            for (int nb = 0; nb < 4; nb++)
                ldsm4(bfr[nb][0], bfr[nb][1], bfr[nb][2], bfr[nb][3],
                      sb + b_ld + ko + nb*1280);

            #pragma unroll
            for (int nb = 0; nb < 4; nb++) {
                #pragma unroll
                for (int mt = 0; mt < 2; mt++) {
                    mma_bf16(acc[mt][nb*2+0], a[mt][0], a[mt][1], a[mt][2], a[mt][3],
                             bfr[nb][0], bfr[nb][1]);
                    mma_bf16(acc[mt][nb*2+1], a[mt][0], a[mt][1], a[mt][2], a[mt][3],
                             bfr[nb][2], bfr[nb][3]);
                }
            }
        }
    }

    const int ncb = n0 + wn;
    float2 bi[8];
    #pragma unroll
    for (int nt = 0; nt < 8; nt++)
        bi[nt] = *(const float2*)(bias + ncb + nt*8 + 2*tg);

    if (IS_QKV) {
        const int which = ncb >> 10;
        const int h = (ncb >> 6) & 15;
        if (which == 2) {
            const int dbase = ncb & 63;
            #pragma unroll
            for (int mt = 0; mt < 2; mt++) {
                #pragma unroll
                for (int hf = 0; hf < 2; hf++) {
                    const int m = m0 + wm + mt*16 + g + hf*8;
                    const int bb = m >> 11, t = m & 2047;
                    __nv_bfloat16* vt = g_vt + ((size_t)(bb*Hn + h) * 64) * Tn + t;
                    #pragma unroll
                    for (int nt = 0; nt < 8; nt++) {
                        const int d = dbase + nt*8 + 2*tg;
                        vt[(size_t)d*Tn]     = __float2bfloat16_rn(acc[mt][nt][hf*2+0] + bi[nt].x);
                        vt[(size_t)(d+1)*Tn] = __float2bfloat16_rn(acc[mt][nt][hf*2+1] + bi[nt].y);
                    }
                }
            }
        } else {
            const float scale = (which == 0) ? 0.125f : 1.f;
            uint32_t* base = (which == 0) ? (uint32_t*)g_q : (uint32_t*)g_k;
            #pragma unroll
            for (int mt = 0; mt < 2; mt++) {
                #pragma unroll
                for (int hf = 0; hf < 2; hf++) {
                    const int m = m0 + wm + mt*16 + g + hf*8;
                    const int b = m >> 11, t = m & 2047;
                    uint32_t* dst = base + ((size_t)(b*Hn + h)*Tn + t) * 32;
                    #pragma unroll
                    for (int nt = 0; nt < 8; nt++)
                        dst[nt*4 + tg] = pack_bf16(
                            (acc[mt][nt][hf*2+0] + bi[nt].x) * scale,
                            (acc[mt][nt][hf*2+1] + bi[nt].y) * scale);
                }
            }
        }
    } else {
        #pragma unroll
        for (int mt = 0; mt < 2; mt++) {
            #pragma unroll
            for (int hf = 0; hf < 2; hf++) {
                const int m = m0 + wm + mt*16 + g + hf*8;
                const float* xr = Xres + (size_t)m * Dn + ncb;
                float* zr = g_z + (size_t)m * Dn + ncb;
                #pragma unroll
                for (int nt = 0; nt < 8; nt++) {
                    const int off = nt*8 + 2*tg;
                    float2 xv = *(const float2*)(xr + off);
                    float2 o;
                    o.x = acc[mt][nt][hf*2+0] + bi[nt].x + xv.x;
                    o.y = acc[mt][nt][hf*2+1] + bi[nt].y + xv.y;
                    *(float2*)(zr + off) = o;
                }
            }
        }
    }
}

// ============================================================
// Causal attention v4: v3 core + per-band named P-barrier +
// qb-major-descending grid (heavies fill wave 1).
// grid = (Hn*Bn, Tn/128): x = head-combo, y = qb reversed.
// ============================================================
#define VW3 36                         // row stride in words (144 B)
#define P_OFF (128*VW3)
#define K_OFF (2*128*VW3)
#define V_OFF (K_OFF + 2*64*VW3)
#define ATT3_W (V_OFF + 2*64*VW3)      // 18432 words = 73728 B

__global__ __launch_bounds__(256, 2) void attn_v4()
{
    extern __shared__ __align__(16) uint32_t smA[];
    __shared__ float dsum[128];

    const int qb = (Tn/128 - 1) - blockIdx.y;     // heavies first (y slow dim)
    const int hb = blockIdx.x;
    const int h = hb & 15, b = hb >> 4;
    const int tid = threadIdx.x, lane = tid & 31, warp = tid >> 5;
    const int g = lane >> 2, tg = lane & 3;
    const int band = warp >> 1, half = warp & 1;
    const int ib  = band * 32;
    const int jd0 = half * 32;

    const size_t headw = ((size_t)(b*Hn + h)) * Tn * 32;
    const uint32_t* qg  = (const uint32_t*)g_q + headw;
    const uint32_t* kg  = (const uint32_t*)g_k + headw;
    const uint32_t* vtg = (const uint32_t*)g_vt + (size_t)(b*Hn + h) * 64 * (Tn/2);

    const uint32_t smb = smem_u32(smA);

    const int lrow15 = lane & 15;
    const int lhi16  = ((lane >> 4) & 1) * 16;
    const int brow   = (lane & 7) + ((lane >> 4) & 1) * 8;
    const int bchk16 = ((lane >> 3) & 1) * 16;

    {
        const int r = tid >> 1, c0 = (tid & 1) * 16;
        const uint32_t dst = smb + (uint32_t)(r*VW3 + c0) * 4;
        const uint32_t* src = qg + (size_t)(qb*128 + r)*32 + c0;
        cp16(dst,      src);
        cp16(dst + 16, src + 4);
        cp16(dst + 32, src + 8);
        cp16(dst + 48, src + 12);
    }
    auto stageKV = [&](int kb, int s) {
        const int bk = K_OFF + s*64*VW3;
        const int bv = V_OFF + s*64*VW3;
        #pragma unroll
        for (int c = 0; c < 2; c++) {
            const int idx = tid*2 + c;
            const int r = idx >> 3, off = (idx & 7) * 4;
            cp16(smb + (uint32_t)(bk + r*VW3 + off) * 4,
                 kg + (size_t)(kb*64 + r)*32 + off);
            cp16(smb + (uint32_t)(bv + r*VW3 + off) * 4,
                 vtg + (size_t)r*(Tn/2) + kb*32 + off);
        }
    };
    stageKV(0, 0);
    CP_COMMIT();
    if (tid < 128) dsum[tid] = 0.f;

    float o[2][4][4];
    #pragma unroll
    for (int mt = 0; mt < 2; mt++)
        #pragma unroll
        for (int nt = 0; nt < 4; nt++)
            #pragma unroll
            for (int e = 0; e < 4; e++) o[mt][nt][e] = 0.f;
    float rs[2][2] = {{0.f,0.f},{0.f,0.f}};

    const int kbmax = 2*qb + 1;
    #pragma unroll 1
    for (int kb = 0; kb <= kbmax; kb++) {
        const int s = kb & 1;
        CP_WAIT0();
        __syncthreads();   // K/V(kb) visible; all PV reads of kb-1 done
        if (kb < kbmax) { stageKV(kb + 1, s ^ 1); CP_COMMIT(); }

        const uint32_t kbase = smb + (uint32_t)(K_OFF + s*64*VW3) * 4;
        const uint32_t vbase = smb + (uint32_t)(V_OFF + s*64*VW3) * 4;

        float sc[2][4][4];
        #pragma unroll
        for (int mt = 0; mt < 2; mt++)
            #pragma unroll
            for (int nt = 0; nt < 4; nt++)
                #pragma unroll
                for (int e = 0; e < 4; e++) sc[mt][nt][e] = 0.f;

        #pragma unroll
        for (int kt = 0; kt < 4; kt++) {
            uint32_t a[2][4];
            #pragma unroll
            for (int mt = 0; mt < 2; mt++)
                ldsm4(a[mt][0], a[mt][1], a[mt][2], a[mt][3],
                      smb + (uint32_t)((ib + mt*16 + lrow15)*VW3)*4 + lhi16 + kt*32);
            #pragma unroll
            for (int p = 0; p < 2; p++) {
                uint32_t b0, b1, b2, b3;
                ldsm4(b0, b1, b2, b3,
                      kbase + (uint32_t)((jd0 + p*16 + brow)*VW3)*4 + bchk16 + kt*32);
                #pragma unroll
                for (int mt = 0; mt < 2; mt++) {
                    mma_bf16(sc[mt][2*p+0], a[mt][0], a[mt][1], a[mt][2], a[mt][3], b0, b1);
                    mma_bf16(sc[mt][2*p+1], a[mt][0], a[mt][1], a[mt][2], a[mt][3], b2, b3);
                }
            }
        }

        const bool edge = (kb >= 2*qb);
        #pragma unroll
        for (int mt = 0; mt < 2; mt++) {
            #pragma unroll
            for (int nt = 0; nt < 4; nt++) {
                const int c = kb*64 + jd0 + nt*8 + 2*tg;
                float p0, p1, p2, p3;
                if (edge) {
                    const int r0g = qb*128 + ib + mt*16 + g;
                    const int r1g = r0g + 8;
                    p0 = (c   <= r0g) ? __expf(sc[mt][nt][0]) : 0.f;
                    p1 = (c+1 <= r0g) ? __expf(sc[mt][nt][1]) : 0.f;
                    p2 = (c   <= r1g) ? __expf(sc[mt][nt][2]) : 0.f;
                    p3 = (c+1 <= r1g) ? __expf(sc[mt][nt][3]) : 0.f;
                } else {
                    p0 = __expf(sc[mt][nt][0]); p1 = __expf(sc[mt][nt][1]);
                    p2 = __expf(sc[mt][nt][2]); p3 = __expf(sc[mt][nt][3]);
                }
                rs[mt][0] += p0 + p1;
                rs[mt][1] += p2 + p3;
                const int jw = (jd0 >> 1) + nt*4 + tg;
                smA[P_OFF + (ib + mt*16 + g    )*VW3 + jw] = pack_bf16(p0, p1);
                smA[P_OFF + (ib + mt*16 + g + 8)*VW3 + jw] = pack_bf16(p2, p3);
            }
        }
        // band-pair barrier: this band's 2 warps wrote this band's P rows;
        // PV below reads only this band's rows. Cross-iter reuse ordered by
        // the CTA-wide barrier at loop top.
        asm volatile("bar.sync %0, 64;" :: "r"(1 + band) : "memory");

        #pragma unroll
        for (int kt = 0; kt < 4; kt++) {
            uint32_t a[2][4];
            #pragma unroll
            for (int mt = 0; mt < 2; mt++)
                ldsm4(a[mt][0], a[mt][1], a[mt][2], a[mt][3],
                      smb + (uint32_t)(P_OFF*4) +
                      (uint32_t)((ib + mt*16 + lrow15)*VW3)*4 + lhi16 + kt*32);
            #pragma unroll
            for (int p = 0; p < 2; p++) {
                uint32_t b0, b1, b2, b3;
                ldsm4(b0, b1, b2, b3,
                      vbase + (uint32_t)((jd0 + p*16 + brow)*VW3)*4 + bchk16 + kt*32);
                #pragma unroll
                for (int mt = 0; mt < 2; mt++) {
                    mma_bf16(o[mt][2*p+0], a[mt][0], a[mt][1], a[mt][2], a[mt][3], b0, b1);
                    mma_bf16(o[mt][2*p+1], a[mt][0], a[mt][1], a[mt][2], a[mt][3], b2, b3);
                }
            }
        }
    }

    #pragma unroll
    for (int mt = 0; mt < 2; mt++) {
        rs[mt][0] += __shfl_xor_sync(0xffffffffu, rs[mt][0], 1);
        rs[mt][0] += __shfl_xor_sync(0xffffffffu, rs[mt][0], 2);
        rs[mt][1] += __shfl_xor_sync(0xffffffffu, rs[mt][1], 1);
        rs[mt][1] += __shfl_xor_sync(0xffffffffu, rs[mt][1], 2);
        if (tg == 0) {
            atomicAdd(&dsum[ib + mt*16 + g],     rs[mt][0]);
            atomicAdd(&dsum[ib + mt*16 + g + 8], rs[mt][1]);
        }
    }
    __syncthreads();

    uint32_t* yb = (uint32_t*)g_yb + ((size_t)(b*Tn + qb*128))*512 + h*32;
    #pragma unroll
    for (int mt = 0; mt < 2; mt++) {
        const float inv0 = 1.f / (dsum[ib + mt*16 + g]     + 1e-9f);
        const float inv1 = 1.f / (dsum[ib + mt*16 + g + 8] + 1e-9f);
        #pragma unroll
        for (int nt = 0; nt < 4; nt++) {
            const int cw = (jd0 >> 1) + nt*4 + tg;
            yb[(size_t)(ib + mt*16 + g    )*512 + cw] = pack_bf16(o[mt][nt][0]*inv0, o[mt][nt][1]*inv0);
            yb[(size_t)(ib + mt*16 + g + 8)*512 + cw] = pack_bf16(o[mt][nt][2]*inv1, o[mt][nt][3]*inv1);
        }
    }
}

// ============================================================
// LayerNorm (dedicated kernel)
// ============================================================
__global__ __launch_bounds__(256) void ln_kernel(
    const float* __restrict__ gamma, const float* __restrict__ beta,
    float* __restrict__ out)
{
    int row = blockIdx.x;
    int tid = threadIdx.x;
    const float* z = g_z + (size_t)row * Dn + tid*4;
    float4 v = *(const float4*)z;
    float s  = v.x + v.y + v.z + v.w;
    float ss = v.x*v.x + v.y*v.y + v.z*v.z + v.w*v.w;

    #pragma unroll
    for (int off = 16; off; off >>= 1) {
        s  += __shfl_xor_sync(0xffffffffu, s,  off);
        ss += __shfl_xor_sync(0xffffffffu, ss, off);
    }

    __shared__ float rsm[8], rss[8];
    __shared__ float smu, srstd;
    int wid = tid >> 5, lane = tid & 31;
    if (lane == 0) { rsm[wid] = s; rss[wid] = ss; }
    __syncthreads();
    if (tid == 0) {
        float S = 0.f, SS = 0.f;
        #pragma unroll
        for (int w = 0; w < 8; w++) { S += rsm[w]; SS += rss[w]; }
        float mu  = S * (1.f / Dn);
        float var = SS * (1.f / Dn) - mu * mu;
        smu = mu;
        srstd = rsqrtf(var + 1e-5f);
    }
    __syncthreads();
    float mu = smu, rstd = srstd;

    float4 g4 = *(const float4*)(gamma + tid*4);
    float4 b4 = *(const float4*)(beta  + tid*4);
    float4 o;
    o.x = (v.x - mu)*rstd*g4.x + b4.x;
    o.y = (v.y - mu)*rstd*g4.y + b4.y;
    o.z = (v.z - mu)*rstd*g4.z + b4.z;
    o.w = (v.w - mu)*rstd*g4.w + b4.w;
    *(float4*)(out + (size_t)row * Dn + tid*4) = o;
}

// ============================================================
extern "C" void kernel_launch(void* const* d_in, const int* in_sizes, int n_in,
                              void* d_out, int out_size)
{
    (void)in_sizes; (void)n_in; (void)out_size;
    const float* x    = (const float*)d_in[0];
    // d_in[1] = attn_mask: deterministic causal, not needed
    const float* Wp   = (const float*)d_in[2];
    const float* bp   = (const float*)d_in[3];
    const float* Wo   = (const float*)d_in[4];
    const float* bo   = (const float*)d_in[5];
    const float* gam  = (const float*)d_in[6];
    const float* bet  = (const float*)d_in[7];
    float* out = (float*)d_out;

    const int SMEM_G = 3 * STG_W * 4;   // 61440 B
    cudaFuncSetAttribute(gemm_mma5<N_QKV, true>,
                         cudaFuncAttributeMaxDynamicSharedMemorySize, SMEM_G);
    cudaFuncSetAttribute(gemm_mma5<Dn, false>,
                         cudaFuncAttributeMaxDynamicSharedMemorySize, SMEM_G);
    const int SMEM_A3 = ATT3_W * 4;     // 73728 B
    cudaFuncSetAttribute(attn_v4,
                         cudaFuncAttributeMaxDynamicSharedMemorySize, SMEM_A3);

    prep_all<<<2048 + 96*32 + 32*32, 256>>>(x, Wp, Wo);

    gemm_mma5<N_QKV, true><<<dim3(N_QKV/128, M_TOT/128), 256, SMEM_G>>>(bp, nullptr);

    attn_v4<<<dim3(Hn*Bn, Tn/128), 256, SMEM_A3>>>();

    gemm_mma5<Dn, false><<<dim3(Dn/128, M_TOT/128), 256, SMEM_G>>>(bo, x);

    ln_kernel<<<M_TOT, 256>>>(gam, bet, out);
}

// round 17
// speedup vs baseline: 1.7020x; 1.0101x over previous
#include <cuda_runtime.h>
#include <cuda_bf16.h>
#include <math.h>
#include <stdint.h>

#define Bn  2
#define Tn  2048
#define Dn  1024
#define Hn  16
#define HDn 64
#define M_TOT 4096
#define N_QKV 3072

// -------- scratch (device globals: allocation-free) --------
__device__ __nv_bfloat16 g_q[(size_t)Bn*Hn*Tn*HDn];           // [b,h][t][d]
__device__ __nv_bfloat16 g_k[(size_t)Bn*Hn*Tn*HDn];           // [b,h][t][d]
__device__ __nv_bfloat16 g_vt[(size_t)Bn*Hn*HDn*Tn];          // [b,h][d][t]
__device__ __nv_bfloat16 g_yb[(size_t)M_TOT*Dn];              // attention out bf16
__device__ __nv_bfloat16 g_xb[(size_t)M_TOT*Dn];              // x bf16
__device__ __nv_bfloat16 g_wpt[(size_t)N_QKV*Dn];             // W_proj^T bf16 [N][K]
__device__ __nv_bfloat16 g_wot[(size_t)Dn*Dn];                // W_out^T  bf16 [N][K]
__device__ float g_z[(size_t)M_TOT*Dn];

// ---------------- helpers ----------------
__device__ __forceinline__ uint32_t pack_bf16(float lo, float hi) {
    uint32_t r;
    asm("cvt.rn.bf16x2.f32 %0, %1, %2;" : "=r"(r) : "f"(hi), "f"(lo));
    return r;
}

__device__ __forceinline__ void mma_bf16(float d[4],
                                         uint32_t a0, uint32_t a1, uint32_t a2, uint32_t a3,
                                         uint32_t b0, uint32_t b1) {
    asm volatile(
        "mma.sync.aligned.m16n8k16.row.col.f32.bf16.bf16.f32 "
        "{%0,%1,%2,%3}, {%4,%5,%6,%7}, {%8,%9}, {%0,%1,%2,%3};\n"
        : "+f"(d[0]), "+f"(d[1]), "+f"(d[2]), "+f"(d[3])
        : "r"(a0), "r"(a1), "r"(a2), "r"(a3), "r"(b0), "r"(b1));
}

__device__ __forceinline__ void ldsm4(uint32_t& r0, uint32_t& r1,
                                      uint32_t& r2, uint32_t& r3, uint32_t addr) {
    asm volatile("ldmatrix.sync.aligned.m8n8.x4.shared.b16 {%0,%1,%2,%3}, [%4];"
                 : "=r"(r0), "=r"(r1), "=r"(r2), "=r"(r3) : "r"(addr));
}

__device__ __forceinline__ uint32_t smem_u32(const void* p) {
    uint32_t a;
    asm("{ .reg .u64 t; cvta.to.shared.u64 t, %1; cvt.u32.u64 %0, t; }"
        : "=r"(a) : "l"(p));
    return a;
}

__device__ __forceinline__ void cp16(uint32_t dst, const void* src) {
    asm volatile("cp.async.cg.shared.global [%0], [%1], 16;"
                 :: "r"(dst), "l"(src) : "memory");
}
#define CP_COMMIT() asm volatile("cp.async.commit_group;" ::: "memory")
#define CP_WAIT1()  asm volatile("cp.async.wait_group 1;" ::: "memory")
#define CP_WAIT0()  asm volatile("cp.async.wait_group 0;" ::: "memory")

// ============================================================
// prep_all: x->bf16, Wp^T, Wo^T — ONE kernel launch
// ============================================================
__device__ __forceinline__ void transpose_block(
    const float* __restrict__ W, uint32_t* __restrict__ Wt,
    int N, int n0, int k0, int tid, float (*tile)[33])
{
    const int tx = tid & 31, ty = tid >> 5;
    #pragma unroll
    for (int p = 0; p < 4; p++) {
        int r = ty + p * 8;
        tile[r][tx] = W[(size_t)(k0 + r) * N + n0 + tx];
    }
    __syncthreads();
    const int wx = tid & 15, wy = tid >> 4;
    #pragma unroll
    for (int p = 0; p < 2; p++) {
        int rowo = wy + p * 16;
        uint32_t wv = pack_bf16(tile[2*wx][rowo], tile[2*wx+1][rowo]);
        Wt[(((size_t)(n0 + rowo) * Dn + k0) >> 1) + wx] = wv;
    }
}

__global__ __launch_bounds__(256) void prep_all(
    const float* __restrict__ x, const float* __restrict__ Wp,
    const float* __restrict__ Wo)
{
    __shared__ float tile[32][33];
    const int id = blockIdx.x;
    const int tid = threadIdx.x;
    if (id < 2048) {
        size_t i = ((size_t)id * 256 + tid) * 8;
        float4 a = *(const float4*)(x + i);
        float4 b = *(const float4*)(x + i + 4);
        uint4 o;
        o.x = pack_bf16(a.x, a.y); o.y = pack_bf16(a.z, a.w);
        o.z = pack_bf16(b.x, b.y); o.w = pack_bf16(b.z, b.w);
        *(uint4*)((uint32_t*)g_xb + (i >> 1)) = o;
    } else if (id < 2048 + 96*32) {
        const int idx = id - 2048;
        transpose_block(Wp, (uint32_t*)g_wpt, N_QKV,
                        (idx % 96) * 32, (idx / 96) * 32, tid, tile);
    } else {
        const int idx = id - (2048 + 96*32);
        transpose_block(Wo, (uint32_t*)g_wot, Dn,
                        (idx % 32) * 32, (idx / 32) * 32, tid, tile);
    }
}

// ============================================================
// bf16 HMMA GEMM v5 (converged config, frozen)
// ============================================================
#define RSW 20                       // row stride words (80 B)
#define AST_W (128*RSW)              // 2560
#define STG_W (2*AST_W)              // 5120 words = 20 KB

template <int ND, bool IS_QKV>
__global__ __launch_bounds__(256, 2) void gemm_mma5(
    const float* __restrict__ bias, const float* __restrict__ Xres)
{
    extern __shared__ __align__(16) uint32_t sm5[];   // 3 * STG_W

    const int tid = threadIdx.x, lane = tid & 31, warp = tid >> 5;
    const int g = lane >> 2, tg = lane & 3;
    const int wm = (warp & 3) * 32;
    const int wn = (warp >> 2) * 64;
    const int m0 = blockIdx.y * 128, n0 = blockIdx.x * 128;

    const uint32_t* Aimg = (const uint32_t*)(IS_QKV ? g_xb : g_yb);
    const uint32_t* Bimg = (const uint32_t*)(IS_QKV ? g_wpt : g_wot);

    const uint32_t smb = smem_u32(sm5);

    const uint32_t a_ld = (wm + (lane & 15)) * 80 + ((lane >> 4) & 1) * 16;
    const uint32_t b_ld = AST_W*4 +
        (wn + (lane & 7) + ((lane >> 4) & 1) * 8) * 80 + ((lane >> 3) & 1) * 16;

    float acc[2][8][4];
    #pragma unroll
    for (int i = 0; i < 2; i++)
        #pragma unroll
        for (int j = 0; j < 8; j++)
            #pragma unroll
            for (int e = 0; e < 4; e++) acc[i][j][e] = 0.f;

    auto stagef = [&](int kt) {
        uint32_t* st = sm5 + (kt % 3) * STG_W;
        #pragma unroll
        for (int p = 0; p < 4; p++) {
            const int idx = tid + p * 256;
            const int r = idx >> 2;
            const int c = (idx & 3) * 4;
            if (r < 128)
                cp16(smem_u32(st + r*RSW + c),
                     Aimg + (size_t)(m0 + r) * (Dn/2) + kt*16 + c);
            else
                cp16(smem_u32(st + AST_W + (r-128)*RSW + c),
                     Bimg + (size_t)(n0 + r - 128) * (Dn/2) + kt*16 + c);
        }
        CP_COMMIT();
    };

    stagef(0); stagef(1);

    #pragma unroll 1
    for (int kt = 0; kt < 32; kt++) {
        if (kt < 31) { CP_WAIT1(); } else { CP_WAIT0(); }
        __syncthreads();
        if (kt + 2 < 32) stagef(kt + 2);

        const uint32_t sb = smb + (uint32_t)(kt % 3) * (STG_W * 4);

        #pragma unroll
        for (int ks = 0; ks < 2; ks++) {
            const uint32_t ko = ks * 32;
            uint32_t a[2][4], bfr[4][4];
            #pragma unroll
            for (int mt = 0; mt < 2; mt++)
                ldsm4(a[mt][0], a[mt][1], a[mt][2], a[mt][3],
                      sb + a_ld + ko + mt*1280);
            #pragma unroll
            for (int nb = 0; nb < 4; nb++)
                ldsm4(bfr[nb][0], bfr[nb][1], bfr[nb][2], bfr[nb][3],
                      sb + b_ld + ko + nb*1280);

            #pragma unroll
            for (int nb = 0; nb < 4; nb++) {
                #pragma unroll
                for (int mt = 0; mt < 2; mt++) {
                    mma_bf16(acc[mt][nb*2+0], a[mt][0], a[mt][1], a[mt][2], a[mt][3],
                             bfr[nb][0], bfr[nb][1]);
                    mma_bf16(acc[mt][nb*2+1], a[mt][0], a[mt][1], a[mt][2], a[mt][3],
                             bfr[nb][2], bfr[nb][3]);
                }
            }
        }
    }

    const int ncb = n0 + wn;
    float2 bi[8];
    #pragma unroll
    for (int nt = 0; nt < 8; nt++)
        bi[nt] = *(const float2*)(bias + ncb + nt*8 + 2*tg);

    if (IS_QKV) {
        const int which = ncb >> 10;
        const int h = (ncb >> 6) & 15;
        if (which == 2) {
            const int dbase = ncb & 63;
            #pragma unroll
            for (int mt = 0; mt < 2; mt++) {
                #pragma unroll
                for (int hf = 0; hf < 2; hf++) {
                    const int m = m0 + wm + mt*16 + g + hf*8;
                    const int bb = m >> 11, t = m & 2047;
                    __nv_bfloat16* vt = g_vt + ((size_t)(bb*Hn + h) * 64) * Tn + t;
                    #pragma unroll
                    for (int nt = 0; nt < 8; nt++) {
                        const int d = dbase + nt*8 + 2*tg;
                        vt[(size_t)d*Tn]     = __float2bfloat16_rn(acc[mt][nt][hf*2+0] + bi[nt].x);
                        vt[(size_t)(d+1)*Tn] = __float2bfloat16_rn(acc[mt][nt][hf*2+1] + bi[nt].y);
                    }
                }
            }
        } else {
            const float scale = (which == 0) ? 0.125f : 1.f;
            uint32_t* base = (which == 0) ? (uint32_t*)g_q : (uint32_t*)g_k;
            #pragma unroll
            for (int mt = 0; mt < 2; mt++) {
                #pragma unroll
                for (int hf = 0; hf < 2; hf++) {
                    const int m = m0 + wm + mt*16 + g + hf*8;
                    const int b = m >> 11, t = m & 2047;
                    uint32_t* dst = base + ((size_t)(b*Hn + h)*Tn + t) * 32;
                    #pragma unroll
                    for (int nt = 0; nt < 8; nt++)
                        dst[nt*4 + tg] = pack_bf16(
                            (acc[mt][nt][hf*2+0] + bi[nt].x) * scale,
                            (acc[mt][nt][hf*2+1] + bi[nt].y) * scale);
                }
            }
        }
    } else {
        #pragma unroll
        for (int mt = 0; mt < 2; mt++) {
            #pragma unroll
            for (int hf = 0; hf < 2; hf++) {
                const int m = m0 + wm + mt*16 + g + hf*8;
                const float* xr = Xres + (size_t)m * Dn + ncb;
                float* zr = g_z + (size_t)m * Dn + ncb;
                #pragma unroll
                for (int nt = 0; nt < 8; nt++) {
                    const int off = nt*8 + 2*tg;
                    float2 xv = *(const float2*)(xr + off);
                    float2 o;
                    o.x = acc[mt][nt][hf*2+0] + bi[nt].x + xv.x;
                    o.y = acc[mt][nt][hf*2+1] + bi[nt].y + xv.y;
                    *(float2*)(zr + off) = o;
                }
            }
        }
    }
}

// ============================================================
// Causal attention v5: v4 + depth-2 KV prefetch (3 K + 3 V buffers).
// grid = (Hn*Bn, Tn/128): x = head-combo, y = qb reversed (heavy first).
// ============================================================
#define VW3 36                         // row stride in words (144 B)
#define P_OFF (128*VW3)
#define K_OFF (2*128*VW3)              // 3 K buffers follow
#define V_OFF (K_OFF + 3*64*VW3)       // 3 V buffers follow
#define ATT5_W (V_OFF + 3*64*VW3)      // 23040 words = 92160 B

__global__ __launch_bounds__(256, 2) void attn_v5()
{
    extern __shared__ __align__(16) uint32_t smA[];
    __shared__ float dsum[128];

    const int qb = (Tn/128 - 1) - blockIdx.y;     // heavies first (y slow dim)
    const int hb = blockIdx.x;
    const int h = hb & 15, b = hb >> 4;
    const int tid = threadIdx.x, lane = tid & 31, warp = tid >> 5;
    const int g = lane >> 2, tg = lane & 3;
    const int band = warp >> 1, half = warp & 1;
    const int ib  = band * 32;
    const int jd0 = half * 32;

    const size_t headw = ((size_t)(b*Hn + h)) * Tn * 32;
    const uint32_t* qg  = (const uint32_t*)g_q + headw;
    const uint32_t* kg  = (const uint32_t*)g_k + headw;
    const uint32_t* vtg = (const uint32_t*)g_vt + (size_t)(b*Hn + h) * 64 * (Tn/2);

    const uint32_t smb = smem_u32(smA);

    const int lrow15 = lane & 15;
    const int lhi16  = ((lane >> 4) & 1) * 16;
    const int brow   = (lane & 7) + ((lane >> 4) & 1) * 8;
    const int bchk16 = ((lane >> 3) & 1) * 16;

    {
        const int r = tid >> 1, c0 = (tid & 1) * 16;
        const uint32_t dst = smb + (uint32_t)(r*VW3 + c0) * 4;
        const uint32_t* src = qg + (size_t)(qb*128 + r)*32 + c0;
        cp16(dst,      src);
        cp16(dst + 16, src + 4);
        cp16(dst + 32, src + 8);
        cp16(dst + 48, src + 12);
    }
    auto stageKV = [&](int kb, int s) {
        const int bk = K_OFF + s*64*VW3;
        const int bv = V_OFF + s*64*VW3;
        #pragma unroll
        for (int c = 0; c < 2; c++) {
            const int idx = tid*2 + c;
            const int r = idx >> 3, off = (idx & 7) * 4;
            cp16(smb + (uint32_t)(bk + r*VW3 + off) * 4,
                 kg + (size_t)(kb*64 + r)*32 + off);
            cp16(smb + (uint32_t)(bv + r*VW3 + off) * 4,
                 vtg + (size_t)r*(Tn/2) + kb*32 + off);
        }
        CP_COMMIT();
    };
    const int kbmax = 2*qb + 1;
    stageKV(0, 0);
    if (kbmax >= 1) stageKV(1, 1);
    if (tid < 128) dsum[tid] = 0.f;

    float o[2][4][4];
    #pragma unroll
    for (int mt = 0; mt < 2; mt++)
        #pragma unroll
        for (int nt = 0; nt < 4; nt++)
            #pragma unroll
            for (int e = 0; e < 4; e++) o[mt][nt][e] = 0.f;
    float rs[2][2] = {{0.f,0.f},{0.f,0.f}};

    #pragma unroll 1
    for (int kb = 0; kb <= kbmax; kb++) {
        const int s = kb % 3;
        if (kb < kbmax) { CP_WAIT1(); } else { CP_WAIT0(); }
        __syncthreads();   // K/V(kb) visible; reads of (kb-1)'s buffer done
        if (kb + 2 <= kbmax) stageKV(kb + 2, (kb + 2) % 3);

        const uint32_t kbase = smb + (uint32_t)(K_OFF + s*64*VW3) * 4;
        const uint32_t vbase = smb + (uint32_t)(V_OFF + s*64*VW3) * 4;

        float sc[2][4][4];
        #pragma unroll
        for (int mt = 0; mt < 2; mt++)
            #pragma unroll
            for (int nt = 0; nt < 4; nt++)
                #pragma unroll
                for (int e = 0; e < 4; e++) sc[mt][nt][e] = 0.f;

        #pragma unroll
        for (int kt = 0; kt < 4; kt++) {
            uint32_t a[2][4];
            #pragma unroll
            for (int mt = 0; mt < 2; mt++)
                ldsm4(a[mt][0], a[mt][1], a[mt][2], a[mt][3],
                      smb + (uint32_t)((ib + mt*16 + lrow15)*VW3)*4 + lhi16 + kt*32);
            #pragma unroll
            for (int p = 0; p < 2; p++) {
                uint32_t b0, b1, b2, b3;
                ldsm4(b0, b1, b2, b3,
                      kbase + (uint32_t)((jd0 + p*16 + brow)*VW3)*4 + bchk16 + kt*32);
                #pragma unroll
                for (int mt = 0; mt < 2; mt++) {
                    mma_bf16(sc[mt][2*p+0], a[mt][0], a[mt][1], a[mt][2], a[mt][3], b0, b1);
                    mma_bf16(sc[mt][2*p+1], a[mt][0], a[mt][1], a[mt][2], a[mt][3], b2, b3);
                }
            }
        }

        const bool edge = (kb >= 2*qb);
        #pragma unroll
        for (int mt = 0; mt < 2; mt++) {
            #pragma unroll
            for (int nt = 0; nt < 4; nt++) {
                const int c = kb*64 + jd0 + nt*8 + 2*tg;
                float p0, p1, p2, p3;
                if (edge) {
                    const int r0g = qb*128 + ib + mt*16 + g;
                    const int r1g = r0g + 8;
                    p0 = (c   <= r0g) ? __expf(sc[mt][nt][0]) : 0.f;
                    p1 = (c+1 <= r0g) ? __expf(sc[mt][nt][1]) : 0.f;
                    p2 = (c   <= r1g) ? __expf(sc[mt][nt][2]) : 0.f;
                    p3 = (c+1 <= r1g) ? __expf(sc[mt][nt][3]) : 0.f;
                } else {
                    p0 = __expf(sc[mt][nt][0]); p1 = __expf(sc[mt][nt][1]);
                    p2 = __expf(sc[mt][nt][2]); p3 = __expf(sc[mt][nt][3]);
                }
                rs[mt][0] += p0 + p1;
                rs[mt][1] += p2 + p3;
                const int jw = (jd0 >> 1) + nt*4 + tg;
                smA[P_OFF + (ib + mt*16 + g    )*VW3 + jw] = pack_bf16(p0, p1);
                smA[P_OFF + (ib + mt*16 + g + 8)*VW3 + jw] = pack_bf16(p2, p3);
            }
        }
        // band-pair barrier: PV reads only this band's P rows.
        asm volatile("bar.sync %0, 64;" :: "r"(1 + band) : "memory");

        #pragma unroll
        for (int kt = 0; kt < 4; kt++) {
            uint32_t a[2][4];
            #pragma unroll
            for (int mt = 0; mt < 2; mt++)
                ldsm4(a[mt][0], a[mt][1], a[mt][2], a[mt][3],
                      smb + (uint32_t)(P_OFF*4) +
                      (uint32_t)((ib + mt*16 + lrow15)*VW3)*4 + lhi16 + kt*32);
            #pragma unroll
            for (int p = 0; p < 2; p++) {
                uint32_t b0, b1, b2, b3;
                ldsm4(b0, b1, b2, b3,
                      vbase + (uint32_t)((jd0 + p*16 + brow)*VW3)*4 + bchk16 + kt*32);
                #pragma unroll
                for (int mt = 0; mt < 2; mt++) {
                    mma_bf16(o[mt][2*p+0], a[mt][0], a[mt][1], a[mt][2], a[mt][3], b0, b1);
                    mma_bf16(o[mt][2*p+1], a[mt][0], a[mt][1], a[mt][2], a[mt][3], b2, b3);
                }
            }
        }
    }

    #pragma unroll
    for (int mt = 0; mt < 2; mt++) {
        rs[mt][0] += __shfl_xor_sync(0xffffffffu, rs[mt][0], 1);
        rs[mt][0] += __shfl_xor_sync(0xffffffffu, rs[mt][0], 2);
        rs[mt][1] += __shfl_xor_sync(0xffffffffu, rs[mt][1], 1);
        rs[mt][1] += __shfl_xor_sync(0xffffffffu, rs[mt][1], 2);
        if (tg == 0) {
            atomicAdd(&dsum[ib + mt*16 + g],     rs[mt][0]);
            atomicAdd(&dsum[ib + mt*16 + g + 8], rs[mt][1]);
        }
    }
    __syncthreads();

    uint32_t* yb = (uint32_t*)g_yb + ((size_t)(b*Tn + qb*128))*512 + h*32;
    #pragma unroll
    for (int mt = 0; mt < 2; mt++) {
        const float inv0 = 1.f / (dsum[ib + mt*16 + g]     + 1e-9f);
        const float inv1 = 1.f / (dsum[ib + mt*16 + g + 8] + 1e-9f);
        #pragma unroll
        for (int nt = 0; nt < 4; nt++) {
            const int cw = (jd0 >> 1) + nt*4 + tg;
            yb[(size_t)(ib + mt*16 + g    )*512 + cw] = pack_bf16(o[mt][nt][0]*inv0, o[mt][nt][1]*inv0);
            yb[(size_t)(ib + mt*16 + g + 8)*512 + cw] = pack_bf16(o[mt][nt][2]*inv1, o[mt][nt][3]*inv1);
        }
    }
}

// ============================================================
// LayerNorm v2: one WARP per row, no barriers, no smem.
// CTA = 256 thr = 8 rows; grid = 512.
// ============================================================
__global__ __launch_bounds__(256) void ln_warp(
    const float* __restrict__ gamma, const float* __restrict__ beta,
    float* __restrict__ out)
{
    const int warp = threadIdx.x >> 5, lane = threadIdx.x & 31;
    const int row = blockIdx.x * 8 + warp;
    const float* z = g_z + (size_t)row * Dn;

    float4 v[8];
    float s = 0.f, ss = 0.f;
    #pragma unroll
    for (int i = 0; i < 8; i++) {
        v[i] = *(const float4*)(z + (lane + i*32) * 4);
        s  += v[i].x + v[i].y + v[i].z + v[i].w;
        ss += v[i].x*v[i].x + v[i].y*v[i].y + v[i].z*v[i].z + v[i].w*v[i].w;
    }
    #pragma unroll
    for (int off = 16; off; off >>= 1) {
        s  += __shfl_xor_sync(0xffffffffu, s,  off);
        ss += __shfl_xor_sync(0xffffffffu, ss, off);
    }
    const float mu   = s * (1.f / Dn);
    const float var  = ss * (1.f / Dn) - mu * mu;
    const float rstd = rsqrtf(var + 1e-5f);

    float* outr = out + (size_t)row * Dn;
    #pragma unroll
    for (int i = 0; i < 8; i++) {
        const int c = (lane + i*32) * 4;
        float4 g4 = *(const float4*)(gamma + c);
        float4 b4 = *(const float4*)(beta  + c);
        float4 o;
        o.x = (v[i].x - mu)*rstd*g4.x + b4.x;
        o.y = (v[i].y - mu)*rstd*g4.y + b4.y;
        o.z = (v[i].z - mu)*rstd*g4.z + b4.z;
        o.w = (v[i].w - mu)*rstd*g4.w + b4.w;
        *(float4*)(outr + c) = o;
    }
}

// ============================================================
extern "C" void kernel_launch(void* const* d_in, const int* in_sizes, int n_in,
                              void* d_out, int out_size)
{
    (void)in_sizes; (void)n_in; (void)out_size;
    const float* x    = (const float*)d_in[0];
    // d_in[1] = attn_mask: deterministic causal, not needed
    const float* Wp   = (const float*)d_in[2];
    const float* bp   = (const float*)d_in[3];
    const float* Wo   = (const float*)d_in[4];
    const float* bo   = (const float*)d_in[5];
    const float* gam  = (const float*)d_in[6];
    const float* bet  = (const float*)d_in[7];
    float* out = (float*)d_out;

    const int SMEM_G = 3 * STG_W * 4;   // 61440 B
    cudaFuncSetAttribute(gemm_mma5<N_QKV, true>,
                         cudaFuncAttributeMaxDynamicSharedMemorySize, SMEM_G);
    cudaFuncSetAttribute(gemm_mma5<Dn, false>,
                         cudaFuncAttributeMaxDynamicSharedMemorySize, SMEM_G);
    const int SMEM_A5 = ATT5_W * 4;     // 92160 B
    cudaFuncSetAttribute(attn_v5,
                         cudaFuncAttributeMaxDynamicSharedMemorySize, SMEM_A5);

    prep_all<<<2048 + 96*32 + 32*32, 256>>>(x, Wp, Wo);

    gemm_mma5<N_QKV, true><<<dim3(N_QKV/128, M_TOT/128), 256, SMEM_G>>>(bp, nullptr);

    attn_v5<<<dim3(Hn*Bn, Tn/128), 256, SMEM_A5>>>();

    gemm_mma5<Dn, false><<<dim3(Dn/128, M_TOT/128), 256, SMEM_G>>>(bo, x);

    ln_warp<<<M_TOT/8, 256>>>(gam, bet, out);
}